// round 11
// baseline (speedup 1.0000x reference)
#include <cuda_runtime.h>
#include <cstdint>

#define Bq 16
#define Nq 4096
#define Sq 1024
#define Kq 32
#define NQ (Bq*Sq)          // 16384 queries
#define NP (Bq*Nq)          // 65536 points
#define NEq (NQ*Kq)         // 524288 rows
#define OUT_PTS (NQ*3)
#define XS_PAD 132
#define QPB 4               // queries per ball block
#define CAP 768             // candidate cap per query (mean 137, sd ~12)
#define BT 256              // ball block threads

// packed fp32x2 helpers (exact IEEE fp32 per lane; only add/mul/fma exist packed)
#define FMA2(d,a,b)   asm("fma.rn.f32x2 %0, %1, %2, %0;" : "+l"(d) : "l"(a), "l"(b))
#define ADD2(d,a,b)   asm("add.rn.f32x2 %0, %1, %2;" : "=l"(d) : "l"(a), "l"(b))
#define MUL2(d,a,b)   asm("mul.rn.f32x2 %0, %1, %2;" : "=l"(d) : "l"(a), "l"(b))
#define PACK2(d,x,y)  asm("mov.b64 %0, {%1, %2};" : "=l"(d) : "f"(x), "f"(y))
#define UNPACK2(x,y,d) asm("mov.b64 {%0, %1}, %2;" : "=f"(x), "=f"(y) : "l"(d))

// ---------------- scratch ----------------
__device__ float  g_sqn[NP];
__device__ float  g_newxyz[NQ*3];
__device__ int    g_grp[NEq];
__device__ float  g_pf[(size_t)NP*64];        // point features (layer0 w/o geom), 16MB
__device__ float  g_y1[(size_t)NEq*64];       // layer1 pre-BN output, 134MB
__device__ float  g_maxv[(size_t)NQ*128];
__device__ float  g_minv[(size_t)NQ*128];
__device__ double g_part[(size_t)256*8192];
__device__ float  g_scale[384];
__device__ float  g_shift[384];

// ---------------- prep: |xyz|^2 exact left-fold ----------------
__global__ void k_prep(const float* __restrict__ xyz) {
    int i = blockIdx.x * blockDim.x + threadIdx.x;
    if (i < NP) {
        float x = xyz[3*i], y = xyz[3*i+1], z = xyz[3*i+2];
        g_sqn[i] = __fadd_rn(__fadd_rn(__fmul_rn(x,x), __fmul_rn(y,y)), __fmul_rn(z,z));
    }
}

// ---------------- FPS: packed f32x2 body, scalar min/argmax, 3-level cross-warp tail ----------------
__global__ void __launch_bounds__(512) k_fps(const float* __restrict__ xyz,
                                             float* __restrict__ out) {
    const int b = blockIdx.x;
    const int t = threadIdx.x;
    const int lane = t & 31, wid = t >> 5;
    const float* xb = xyz + b*Nq*3;
    // pair j: points p0 = t + 2j*512 (lane0) and p1 = p0 + 512 (lane1); p0 < p1
    unsigned long long px2[4], py2[4], pz2[4];
    float dd[8];
    #pragma unroll
    for (int j = 0; j < 4; j++) {
        int p0 = t + (2*j)*512, p1 = p0 + 512;
        PACK2(px2[j], xb[3*p0],   xb[3*p1]);
        PACK2(py2[j], xb[3*p0+1], xb[3*p1+1]);
        PACK2(pz2[j], xb[3*p0+2], xb[3*p1+2]);
        dd[2*j] = 1e10f; dd[2*j+1] = 1e10f;
    }
    __shared__ unsigned long long swk[2][16];   // double-buffered warp partials
    int far = 0;
    for (int i = 0; i < Sq; i++) {
        float cx = xb[3*far], cy = xb[3*far+1], cz = xb[3*far+2];
        if (t == 0) {
            int o = (b*Sq + i)*3;
            g_newxyz[o] = cx; g_newxyz[o+1] = cy; g_newxyz[o+2] = cz;
            out[o] = cx; out[o+1] = cy; out[o+2] = cz;
        }
        float ncx = -cx, ncy = -cy, ncz = -cz;   // x - c == x + (-c) exactly
        unsigned long long ncx2, ncy2, ncz2;
        PACK2(ncx2, ncx, ncx); PACK2(ncy2, ncy, ncy); PACK2(ncz2, ncz, ncz);
        float bv = -1.0f; int bi = 0;
        #pragma unroll
        for (int j = 0; j < 4; j++) {
            unsigned long long dx, dy, dz, sx, sy, sz, sA, sB;
            ADD2(dx, px2[j], ncx2);
            ADD2(dy, py2[j], ncy2);
            ADD2(dz, pz2[j], ncz2);
            MUL2(sx, dx, dx);
            MUL2(sy, dy, dy);
            MUL2(sz, dz, dz);
            ADD2(sA, sx, sy);        // (dx^2 + dy^2)
            ADD2(sB, sA, sz);        // + dz^2 — exact reference fold per lane
            float d0, d1; UNPACK2(d0, d1, sB);
            float nd0 = fminf(dd[2*j], d0);   dd[2*j]   = nd0;
            if (nd0 > bv) { bv = nd0; bi = t + (2*j)*512; }     // strict > keeps lowest idx
            float nd1 = fminf(dd[2*j+1], d1); dd[2*j+1] = nd1;
            if (nd1 > bv) { bv = nd1; bi = t + (2*j+1)*512; }
        }
        unsigned long long key = ((unsigned long long)__float_as_uint(bv) << 32)
                               | (unsigned)(~(unsigned)bi);
        #pragma unroll
        for (int off = 16; off; off >>= 1) {
            unsigned long long o = __shfl_down_sync(0xffffffffu, key, off);
            if (o > key) key = o;
        }
        const int par = i & 1;
        if (lane == 0) swk[par][wid] = key;
        __syncthreads();
        // 3-level cross-warp: each lane loads TWO partials (overlapped LDS), then 3 xor levels
        unsigned long long kA = swk[par][lane & 7];
        unsigned long long kB = swk[par][(lane & 7) + 8];
        unsigned long long k2 = (kA > kB) ? kA : kB;
        #pragma unroll
        for (int off = 4; off; off >>= 1) {
            unsigned long long o = __shfl_xor_sync(0xffffffffu, k2, off);
            if (o > k2) k2 = o;
        }
        far = (int)(~(unsigned)k2);
    }
}

// ---------------- ball query: 4 queries/block, 256 threads, compact + O(cnt^2) rank ----------------
__global__ void __launch_bounds__(BT) k_ball(const float* __restrict__ xyz) {
    const int blk = blockIdx.x;
    const int q0 = blk * QPB;
    const int b = q0 >> 10;
    const int t = threadIdx.x;
    __shared__ unsigned long long ck[QPB][CAP];
    __shared__ int scnt[QPB];
    __shared__ int sm_m[QPB];
    __shared__ int ssel[QPB][Kq];
    if (t < QPB) scnt[t] = 0;
    __syncthreads();
    float cx[QPB], cy[QPB], cz[QPB], sa[QPB];
    #pragma unroll
    for (int j = 0; j < QPB; j++) {
        cx[j] = g_newxyz[3*(q0+j)]; cy[j] = g_newxyz[3*(q0+j)+1]; cz[j] = g_newxyz[3*(q0+j)+2];
        sa[j] = __fadd_rn(__fadd_rn(__fmul_rn(cx[j],cx[j]), __fmul_rn(cy[j],cy[j])), __fmul_rn(cz[j],cz[j]));
    }
    const float* xb = xyz + b*Nq*3;
    const float* sq = g_sqn + b*Nq;
    for (int n = t; n < Nq; n += BT) {
        float x = xb[3*n], y = xb[3*n+1], z = xb[3*n+2];
        float sn = sq[n];
        #pragma unroll
        for (int j = 0; j < QPB; j++) {
            float dot = __fadd_rn(__fadd_rn(__fmul_rn(x,cx[j]), __fmul_rn(y,cy[j])), __fmul_rn(z,cz[j]));
            float d = __fsub_rn(__fadd_rn(sa[j], sn), __fmul_rn(2.0f, dot));
            if (d <= 0.04f) {
                unsigned ub = __float_as_uint(d);
                ub = ((int)ub < 0) ? ~ub : (ub | 0x80000000u);   // monotone float->uint
                int p = atomicAdd(&scnt[j], 1);
                if (p < CAP) ck[j][p] = ((unsigned long long)ub << 32) | (unsigned)n;
            }
        }
    }
    __syncthreads();
    #pragma unroll
    for (int j = 0; j < QPB; j++) {
        int cnt = scnt[j]; if (cnt > CAP) cnt = CAP;
        if (t == 0) sm_m[j] = cnt < Kq ? cnt : Kq;
        for (int p = t; p < cnt; p += BT) {
            unsigned long long mk = ck[j][p];
            int r = 0;
            for (int i = 0; i < cnt; i++) r += (ck[j][i] < mk);   // broadcast LDS
            if (r < Kq) ssel[j][r] = (int)(unsigned)mk;
        }
    }
    __syncthreads();
    if (t < QPB*Kq) {
        int j = t >> 5, k = t & 31;
        g_grp[(q0+j)*Kq + k] = ssel[j][k < sm_m[j] ? k : 0];
    }
}

// ---------------- point-feature GEMM (FFMA2 mainloop, R7) ----------------
__global__ void __launch_bounds__(128) k_pf(const float* __restrict__ points,
                                            const float* __restrict__ W0) {
    extern __shared__ float sm[];
    float* xs = sm;                   // [64][XS_PAD]
    float* Wt = sm + 64*XS_PAD;       // [64][64]
    const int t = threadIdx.x;
    const int blk = blockIdx.x;
    for (int i = t; i < 4096; i += 128) Wt[i] = W0[(i & 63)*67 + 3 + (i >> 6)];
    const float4* pts4 = (const float4*)points;
    #pragma unroll
    for (int jj = 0; jj < 16; jj++) {
        int idx = t + jj*128;
        int r = idx >> 4, c4 = idx & 15;
        float4 v = pts4[(size_t)(blk*128 + r)*16 + c4];
        xs[(4*c4+0)*XS_PAD + r] = v.x;
        xs[(4*c4+1)*XS_PAD + r] = v.y;
        xs[(4*c4+2)*XS_PAD + r] = v.z;
        xs[(4*c4+3)*XS_PAD + r] = v.w;
    }
    __syncthreads();
    const int r0 = (t & 15)*8, o0 = (t >> 4)*8;
    unsigned long long acc2[8][4];
    #pragma unroll
    for (int i = 0; i < 8; i++)
        #pragma unroll
        for (int j = 0; j < 4; j++) acc2[i][j] = 0ull;
    for (int c = 0; c < 64; c++) {
        float4 xa = *(const float4*)&xs[c*XS_PAD + r0];
        float4 xc = *(const float4*)&xs[c*XS_PAD + r0 + 4];
        ulonglong2 wA = *(const ulonglong2*)&Wt[c*64 + o0];
        ulonglong2 wB = *(const ulonglong2*)&Wt[c*64 + o0 + 4];
        unsigned long long wp[4] = {wA.x, wA.y, wB.x, wB.y};
        float xr[8] = {xa.x,xa.y,xa.z,xa.w,xc.x,xc.y,xc.z,xc.w};
        unsigned long long xp[8];
        #pragma unroll
        for (int i = 0; i < 8; i++) PACK2(xp[i], xr[i], xr[i]);
        #pragma unroll
        for (int i = 0; i < 8; i++)
            #pragma unroll
            for (int j = 0; j < 4; j++) FMA2(acc2[i][j], xp[i], wp[j]);
    }
    #pragma unroll
    for (int i = 0; i < 8; i++) {
        size_t base = ((size_t)(blk*128 + r0 + i))*64 + o0;
        *(ulonglong2*)&g_pf[base]   = make_ulonglong2(acc2[i][0], acc2[i][1]);
        *(ulonglong2*)&g_pf[base+4] = make_ulonglong2(acc2[i][2], acc2[i][3]);
    }
}

// ---------------- layer0 stats: vectorized gather (LDG.128, warp-coalesced rows) ----------------
__global__ void __launch_bounds__(256) k_l0stats(const float* __restrict__ xyz,
                                                 const float* __restrict__ W0,
                                                 const float* __restrict__ b0) {
    __shared__ int   sgp[256];
    __shared__ float sdx[256], sdy[256], sdz[256];
    __shared__ float swx[64], swy[64], swz[64], sb[64];
    __shared__ float ps[64][17], pq[64][17];
    const int t = threadIdx.x;
    const int blk = blockIdx.x;
    if (t < 64) {
        swx[t] = W0[t*67+0]; swy[t] = W0[t*67+1]; swz[t] = W0[t*67+2]; sb[t] = b0[t];
    }
    {
        int R = blk*256 + t;
        int q = R >> 5, b = q >> 10;
        int gp = b*Nq + g_grp[R];
        sgp[t] = gp;
        sdx[t] = __fsub_rn(xyz[gp*3+0], g_newxyz[3*q+0]);
        sdy[t] = __fsub_rn(xyz[gp*3+1], g_newxyz[3*q+1]);
        sdz[t] = __fsub_rn(xyz[gp*3+2], g_newxyz[3*q+2]);
    }
    __syncthreads();
    const int cg = t & 15, rg = t >> 4;
    const int c0 = cg*4;
    float wx[4], wy[4], wz[4], bb[4];
    #pragma unroll
    for (int k = 0; k < 4; k++) { wx[k]=swx[c0+k]; wy[k]=swy[c0+k]; wz[k]=swz[c0+k]; bb[k]=sb[c0+k]; }
    float s[4] = {0,0,0,0}, s2[4] = {0,0,0,0};
    const float4* pf4 = (const float4*)g_pf;
    #pragma unroll 4
    for (int rr = 0; rr < 16; rr++) {
        int r = rg*16 + rr;
        float4 p = pf4[(size_t)sgp[r]*16 + cg];
        float dx = sdx[r], dy = sdy[r], dz = sdz[r];
        float pv[4] = {p.x, p.y, p.z, p.w};
        #pragma unroll
        for (int k = 0; k < 4; k++) {
            float y = pv[k] + fmaf(dx, wx[k], fmaf(dy, wy[k], fmaf(dz, wz[k], bb[k])));
            s[k] += y; s2[k] = fmaf(y, y, s2[k]);
        }
    }
    #pragma unroll
    for (int k = 0; k < 4; k++) { ps[c0+k][rg] = s[k]; pq[c0+k][rg] = s2[k]; }
    __syncthreads();
    if (t < 64) {
        double S = 0.0, Q = 0.0;
        #pragma unroll
        for (int g = 0; g < 16; g++) { S += (double)ps[t][g]; Q += (double)pq[t][g]; }
        g_part[(size_t)t*8192 + blk]       = S;
        g_part[(size_t)(128+t)*8192 + blk] = Q;
    }
}

// ---------------- BN finalize ----------------
__global__ void __launch_bounds__(256) k_fin(const float* __restrict__ ga,
                                             const float* __restrict__ be,
                                             int off, int nblk) {
    const int ch = blockIdx.x;
    const int t = threadIdx.x;
    double s = 0.0, s2 = 0.0;
    const double* p0 = g_part + (size_t)ch*8192;
    const double* p1 = g_part + (size_t)(128+ch)*8192;
    for (int i = t; i < nblk; i += 256) { s += p0[i]; s2 += p1[i]; }
    __shared__ double sh[256], sh2[256];
    sh[t] = s; sh2[t] = s2; __syncthreads();
    for (int o = 128; o; o >>= 1) {
        if (t < o) { sh[t] += sh[t+o]; sh2[t] += sh2[t+o]; }
        __syncthreads();
    }
    if (t == 0) {
        double mu  = sh[0]  / (double)NEq;
        double var = sh2[0] / (double)NEq - mu*mu;
        if (var < 0.0) var = 0.0;
        double sc = (double)ga[ch] / sqrt(var + 1e-5);
        g_scale[off+ch] = (float)sc;
        g_shift[off+ch] = (float)((double)be[ch] - mu*sc);
    }
}

// ---------------- layer1 (FFMA2 + lazy epilogue, R7) ----------------
__global__ void __launch_bounds__(128) k_layer1(const float* __restrict__ xyz,
                                                const float* __restrict__ W0,
                                                const float* __restrict__ b0,
                                                const float* __restrict__ W1,
                                                const float* __restrict__ b1) {
    extern __shared__ float sm[];
    float* xs  = sm;                   // [64][XS_PAD]
    float* Wt  = sm + 64*XS_PAD;       // [64][64]
    float* swx = Wt + 4096;
    float* swy = swx + 64; float* swz = swy + 64; float* sb = swz + 64;
    float* ssc = sb + 64;  float* ssh = ssc + 64;
    const int t = threadIdx.x;
    const int blk = blockIdx.x;
    for (int i = t; i < 4096; i += 128) Wt[i] = W1[(i & 63)*64 + (i >> 6)];
    if (t < 64) {
        swx[t] = W0[t*67+0]; swy[t] = W0[t*67+1]; swz[t] = W0[t*67+2];
        sb[t] = b0[t]; ssc[t] = g_scale[t]; ssh[t] = g_shift[t];
    }
    int R = blk*128 + t;
    int q = R >> 5, b = q >> 10;
    int gp = b*Nq + g_grp[R];
    float dx = __fsub_rn(xyz[gp*3+0], g_newxyz[3*q+0]);
    float dy = __fsub_rn(xyz[gp*3+1], g_newxyz[3*q+1]);
    float dz = __fsub_rn(xyz[gp*3+2], g_newxyz[3*q+2]);
    __syncthreads();
    const float4* pfv4 = (const float4*)g_pf;
    #pragma unroll
    for (int c4 = 0; c4 < 16; c4++) {
        float4 p = pfv4[(size_t)gp*16 + c4];
        float pv[4] = {p.x, p.y, p.z, p.w};
        #pragma unroll
        for (int k2 = 0; k2 < 4; k2++) {
            int c = c4*4 + k2;
            float y = pv[k2] + fmaf(dx, swx[c], fmaf(dy, swy[c], fmaf(dz, swz[c], sb[c])));
            xs[c*XS_PAD + t] = fmaxf(fmaf(ssc[c], y, ssh[c]), 0.0f);
        }
    }
    __syncthreads();
    const int r0 = (t & 15)*8, o0 = (t >> 4)*8;
    unsigned long long acc2[8][4];
    {
        ulonglong2 bA = *(const ulonglong2*)&b1[o0];
        ulonglong2 bB = *(const ulonglong2*)&b1[o0+4];
        unsigned long long bp[4] = {bA.x, bA.y, bB.x, bB.y};
        #pragma unroll
        for (int i = 0; i < 8; i++)
            #pragma unroll
            for (int j = 0; j < 4; j++) acc2[i][j] = bp[j];
    }
    for (int c = 0; c < 64; c++) {
        float4 xa = *(const float4*)&xs[c*XS_PAD + r0];
        float4 xc = *(const float4*)&xs[c*XS_PAD + r0 + 4];
        ulonglong2 wA = *(const ulonglong2*)&Wt[c*64 + o0];
        ulonglong2 wB = *(const ulonglong2*)&Wt[c*64 + o0 + 4];
        unsigned long long wp[4] = {wA.x, wA.y, wB.x, wB.y};
        float xr[8] = {xa.x,xa.y,xa.z,xa.w,xc.x,xc.y,xc.z,xc.w};
        unsigned long long xp[8];
        #pragma unroll
        for (int i = 0; i < 8; i++) PACK2(xp[i], xr[i], xr[i]);
        #pragma unroll
        for (int i = 0; i < 8; i++)
            #pragma unroll
            for (int j = 0; j < 4; j++) FMA2(acc2[i][j], xp[i], wp[j]);
    }
    #pragma unroll
    for (int i = 0; i < 8; i++) {
        size_t base = ((size_t)(blk*128 + r0 + i))*64 + o0;
        *(ulonglong2*)&g_y1[base]   = make_ulonglong2(acc2[i][0], acc2[i][1]);
        *(ulonglong2*)&g_y1[base+4] = make_ulonglong2(acc2[i][2], acc2[i][3]);
    }
    #pragma unroll
    for (int jp = 0; jp < 4; jp++) {
        float s0 = 0.0f, q0s = 0.0f, s1 = 0.0f, q1s = 0.0f;
        #pragma unroll
        for (int i = 0; i < 8; i++) {
            float a0, a1; UNPACK2(a0, a1, acc2[i][jp]);
            s0 += a0; q0s = fmaf(a0, a0, q0s);
            s1 += a1; q1s = fmaf(a1, a1, q1s);
        }
        #pragma unroll
        for (int off = 8; off; off >>= 1) {
            s0  += __shfl_down_sync(0xffffffffu, s0,  off, 16);
            q0s += __shfl_down_sync(0xffffffffu, q0s, off, 16);
            s1  += __shfl_down_sync(0xffffffffu, s1,  off, 16);
            q1s += __shfl_down_sync(0xffffffffu, q1s, off, 16);
        }
        if ((t & 15) == 0) {
            g_part[(size_t)(o0+2*jp)*8192 + blk]       = (double)s0;
            g_part[(size_t)(128+o0+2*jp)*8192 + blk]   = (double)q0s;
            g_part[(size_t)(o0+2*jp+1)*8192 + blk]     = (double)s1;
            g_part[(size_t)(128+o0+2*jp+1)*8192 + blk] = (double)q1s;
        }
    }
}

// ---------------- layer2 (FFMA2 + lazy epilogue, R7) ----------------
__global__ void __launch_bounds__(256, 2) k_layer2(const float* __restrict__ W2,
                                                   const float* __restrict__ b2) {
    extern __shared__ float sm[];
    float* xs  = sm;                   // [64][XS_PAD]
    float* Wt  = sm + 64*XS_PAD;       // [64][128]
    float* ssc = Wt + 8192;
    float* ssh = ssc + 64;
    const int t = threadIdx.x;
    const int blk = blockIdx.x;
    for (int i = t; i < 8192; i += 256) Wt[i] = W2[(i & 127)*64 + (i >> 7)];
    if (t < 64) { ssc[t] = g_scale[128+t]; ssh[t] = g_shift[128+t]; }
    __syncthreads();
    const float4* y1v = (const float4*)g_y1;
    #pragma unroll
    for (int jj = 0; jj < 8; jj++) {
        int idx = t + jj*256;
        int r = idx >> 4, c4 = idx & 15;
        float4 v = y1v[(size_t)(blk*128 + r)*16 + c4];
        float pv[4] = {v.x, v.y, v.z, v.w};
        #pragma unroll
        for (int k2 = 0; k2 < 4; k2++) {
            int c = c4*4 + k2;
            xs[c*XS_PAD + r] = fmaxf(fmaf(ssc[c], pv[k2], ssh[c]), 0.0f);
        }
    }
    __syncthreads();
    const int r0 = (t & 15)*8, o0 = (t >> 4)*8;
    unsigned long long acc2[8][4];
    {
        ulonglong2 bA = *(const ulonglong2*)&b2[o0];
        ulonglong2 bB = *(const ulonglong2*)&b2[o0+4];
        unsigned long long bp[4] = {bA.x, bA.y, bB.x, bB.y};
        #pragma unroll
        for (int i = 0; i < 8; i++)
            #pragma unroll
            for (int j = 0; j < 4; j++) acc2[i][j] = bp[j];
    }
    for (int c = 0; c < 64; c++) {
        float4 xa = *(const float4*)&xs[c*XS_PAD + r0];
        float4 xc = *(const float4*)&xs[c*XS_PAD + r0 + 4];
        ulonglong2 wA = *(const ulonglong2*)&Wt[c*128 + o0];
        ulonglong2 wB = *(const ulonglong2*)&Wt[c*128 + o0 + 4];
        unsigned long long wp[4] = {wA.x, wA.y, wB.x, wB.y};
        float xr[8] = {xa.x,xa.y,xa.z,xa.w,xc.x,xc.y,xc.z,xc.w};
        unsigned long long xp[8];
        #pragma unroll
        for (int i = 0; i < 8; i++) PACK2(xp[i], xr[i], xr[i]);
        #pragma unroll
        for (int i = 0; i < 8; i++)
            #pragma unroll
            for (int j = 0; j < 4; j++) FMA2(acc2[i][j], xp[i], wp[j]);
    }
    #pragma unroll
    for (int jp = 0; jp < 4; jp++) {
        float a0, a1; UNPACK2(a0, a1, acc2[0][jp]);
        float s0 = a0, q0s = a0*a0, mx0 = a0, mn0 = a0;
        float s1 = a1, q1s = a1*a1, mx1 = a1, mn1 = a1;
        #pragma unroll
        for (int i = 1; i < 8; i++) {
            UNPACK2(a0, a1, acc2[i][jp]);
            s0 += a0; q0s = fmaf(a0, a0, q0s); mx0 = fmaxf(mx0, a0); mn0 = fminf(mn0, a0);
            s1 += a1; q1s = fmaf(a1, a1, q1s); mx1 = fmaxf(mx1, a1); mn1 = fminf(mn1, a1);
        }
        #pragma unroll
        for (int off = 8; off; off >>= 1) {
            s0  += __shfl_down_sync(0xffffffffu, s0,  off, 16);
            q0s += __shfl_down_sync(0xffffffffu, q0s, off, 16);
            s1  += __shfl_down_sync(0xffffffffu, s1,  off, 16);
            q1s += __shfl_down_sync(0xffffffffu, q1s, off, 16);
        }
        if ((t & 15) == 0) {
            g_part[(size_t)(o0+2*jp)*8192 + blk]       = (double)s0;
            g_part[(size_t)(128+o0+2*jp)*8192 + blk]   = (double)q0s;
            g_part[(size_t)(o0+2*jp+1)*8192 + blk]     = (double)s1;
            g_part[(size_t)(128+o0+2*jp+1)*8192 + blk] = (double)q1s;
        }
        #pragma unroll
        for (int off = 2; off; off >>= 1) {
            mx0 = fmaxf(mx0, __shfl_down_sync(0xffffffffu, mx0, off, 4));
            mn0 = fminf(mn0, __shfl_down_sync(0xffffffffu, mn0, off, 4));
            mx1 = fmaxf(mx1, __shfl_down_sync(0xffffffffu, mx1, off, 4));
            mn1 = fminf(mn1, __shfl_down_sync(0xffffffffu, mn1, off, 4));
        }
        if ((t & 3) == 0) {
            int qg = blk*4 + ((t & 15) >> 2);
            g_maxv[(size_t)qg*128 + o0 + 2*jp]     = mx0;
            g_minv[(size_t)qg*128 + o0 + 2*jp]     = mn0;
            g_maxv[(size_t)qg*128 + o0 + 2*jp + 1] = mx1;
            g_minv[(size_t)qg*128 + o0 + 2*jp + 1] = mn1;
        }
    }
}

// ---------------- final: BN2+ReLU fused max-pool from min/max ----------------
__global__ void __launch_bounds__(256) k_maxpool(float* __restrict__ out) {
    int i = blockIdx.x*256 + threadIdx.x;
    int o = i & 127;
    float sc = g_scale[256+o], sh = g_shift[256+o];
    float v = (sc >= 0.0f) ? g_maxv[i] : g_minv[i];
    out[OUT_PTS + i] = fmaxf(fmaf(sc, v, sh), 0.0f);
}

// ---------------- launch: sequential spine; pf overlapped with ball only ----------------
extern "C" void kernel_launch(void* const* d_in, const int* in_sizes, int n_in,
                              void* d_out, int out_size) {
    (void)in_sizes; (void)n_in; (void)out_size;
    const float* xyz    = (const float*)d_in[0];
    const float* points = (const float*)d_in[1];
    const float* W0  = (const float*)d_in[2];
    const float* b0  = (const float*)d_in[3];
    const float* g0  = (const float*)d_in[4];
    const float* bt0 = (const float*)d_in[5];
    const float* W1  = (const float*)d_in[6];
    const float* b1  = (const float*)d_in[7];
    const float* g1  = (const float*)d_in[8];
    const float* bt1 = (const float*)d_in[9];
    const float* W2  = (const float*)d_in[10];
    const float* b2  = (const float*)d_in[11];
    const float* g2  = (const float*)d_in[12];
    const float* bt2 = (const float*)d_in[13];
    float* out = (float*)d_out;

    static cudaStream_t s2 = nullptr;
    static cudaEvent_t ev_fork = nullptr, ev_join = nullptr;
    if (!s2) {   // first call happens BEFORE graph capture
        cudaStreamCreateWithFlags(&s2, cudaStreamNonBlocking);
        cudaEventCreateWithFlags(&ev_fork, cudaEventDisableTiming);
        cudaEventCreateWithFlags(&ev_join, cudaEventDisableTiming);
    }

    const int SM_PF = (64*XS_PAD + 64*64) * 4;
    const int SM_L1 = (64*XS_PAD + 64*64 + 6*64) * 4;
    const int SM_L2 = (64*XS_PAD + 64*128 + 2*64) * 4;
    cudaFuncSetAttribute(k_pf,     cudaFuncAttributeMaxDynamicSharedMemorySize, SM_PF);
    cudaFuncSetAttribute(k_layer1, cudaFuncAttributeMaxDynamicSharedMemorySize, SM_L1);
    cudaFuncSetAttribute(k_layer2, cudaFuncAttributeMaxDynamicSharedMemorySize, SM_L2);

    // sequential: prep -> FPS (latency-critical, runs alone)
    k_prep<<<(NP + 255)/256, 256>>>(xyz);
    k_fps<<<Bq, 512>>>(xyz, out);

    // fork AFTER FPS: pf (fma-bound) overlaps ball (alu-bound); no latency-critical victim
    cudaEventRecord(ev_fork, 0);
    cudaStreamWaitEvent(s2, ev_fork, 0);
    k_pf<<<NP/128, 128, SM_PF, s2>>>(points, W0);
    cudaEventRecord(ev_join, s2);

    k_ball<<<NQ/QPB, BT>>>(xyz);
    cudaStreamWaitEvent(0, ev_join, 0);   // l0stats needs g_pf + g_grp

    k_l0stats<<<NEq/256, 256>>>(xyz, W0, b0);
    k_fin<<<64, 256>>>(g0, bt0, 0, NEq/256);
    k_layer1<<<NEq/128, 128, SM_L1>>>(xyz, W0, b0, W1, b1);
    k_fin<<<64, 256>>>(g1, bt1, 128, NEq/128);
    k_layer2<<<NEq/128, 256, SM_L2>>>(W2, b2);
    k_fin<<<128, 256>>>(g2, bt2, 256, NEq/128);
    k_maxpool<<<NQ*128/256, 256>>>(out);
}

// round 12
// speedup vs baseline: 1.0097x; 1.0097x over previous
#include <cuda_runtime.h>
#include <cstdint>

#define Bq 16
#define Nq 4096
#define Sq 1024
#define Kq 32
#define NQ (Bq*Sq)          // 16384 queries
#define NP (Bq*Nq)          // 65536 points
#define NEq (NQ*Kq)         // 524288 rows
#define OUT_PTS (NQ*3)
#define XS_PAD 132
#define QPB 4               // queries per ball block
#define CAP 768             // candidate cap per query (mean 137, sd ~12)
#define BT 256              // ball block threads

// packed fp32x2 helpers (exact IEEE fp32 per lane; only add/mul/fma exist packed)
#define FMA2(d,a,b)   asm("fma.rn.f32x2 %0, %1, %2, %0;" : "+l"(d) : "l"(a), "l"(b))
#define ADD2(d,a,b)   asm("add.rn.f32x2 %0, %1, %2;" : "=l"(d) : "l"(a), "l"(b))
#define MUL2(d,a,b)   asm("mul.rn.f32x2 %0, %1, %2;" : "=l"(d) : "l"(a), "l"(b))
#define PACK2(d,x,y)  asm("mov.b64 %0, {%1, %2};" : "=l"(d) : "f"(x), "f"(y))
#define UNPACK2(x,y,d) asm("mov.b64 {%0, %1}, %2;" : "=f"(x), "=f"(y) : "l"(d))

// ---------------- scratch ----------------
__device__ float  g_sqn[NP];
__device__ float  g_newxyz[NQ*3];
__device__ int    g_grp[NEq];
__device__ float  g_pf[(size_t)NP*64];        // point features (layer0 w/o geom), 16MB
__device__ float  g_y1[(size_t)NEq*64];       // layer1 pre-BN output, 134MB
__device__ float  g_maxv[(size_t)NQ*128];
__device__ float  g_minv[(size_t)NQ*128];
__device__ double g_part[(size_t)256*8192];
__device__ float  g_scale[384];
__device__ float  g_shift[384];

// ---------------- prep: |xyz|^2 exact left-fold ----------------
__global__ void k_prep(const float* __restrict__ xyz) {
    int i = blockIdx.x * blockDim.x + threadIdx.x;
    if (i < NP) {
        float x = xyz[3*i], y = xyz[3*i+1], z = xyz[3*i+2];
        g_sqn[i] = __fadd_rn(__fadd_rn(__fmul_rn(x,x), __fmul_rn(y,y)), __fmul_rn(z,z));
    }
}

// ---------------- FPS: packed f32x2 body, scalar min/argmax, R10 tail ----------------
__global__ void __launch_bounds__(512) k_fps(const float* __restrict__ xyz,
                                             float* __restrict__ out) {
    const int b = blockIdx.x;
    const int t = threadIdx.x;
    const int lane = t & 31, wid = t >> 5;
    const float* xb = xyz + b*Nq*3;
    // pair j: points p0 = t + 2j*512 (lane0) and p1 = p0 + 512 (lane1); p0 < p1
    unsigned long long px2[4], py2[4], pz2[4];
    float dd[8];
    #pragma unroll
    for (int j = 0; j < 4; j++) {
        int p0 = t + (2*j)*512, p1 = p0 + 512;
        PACK2(px2[j], xb[3*p0],   xb[3*p1]);
        PACK2(py2[j], xb[3*p0+1], xb[3*p1+1]);
        PACK2(pz2[j], xb[3*p0+2], xb[3*p1+2]);
        dd[2*j] = 1e10f; dd[2*j+1] = 1e10f;
    }
    __shared__ unsigned long long swk[2][16];   // double-buffered warp partials
    int far = 0;
    for (int i = 0; i < Sq; i++) {
        float cx = xb[3*far], cy = xb[3*far+1], cz = xb[3*far+2];
        if (t == 0) {
            int o = (b*Sq + i)*3;
            g_newxyz[o] = cx; g_newxyz[o+1] = cy; g_newxyz[o+2] = cz;
            out[o] = cx; out[o+1] = cy; out[o+2] = cz;
        }
        float ncx = -cx, ncy = -cy, ncz = -cz;   // x - c == x + (-c) exactly
        unsigned long long ncx2, ncy2, ncz2;
        PACK2(ncx2, ncx, ncx); PACK2(ncy2, ncy, ncy); PACK2(ncz2, ncz, ncz);
        float bv = -1.0f; int bi = 0;
        #pragma unroll
        for (int j = 0; j < 4; j++) {
            unsigned long long dx, dy, dz, sx, sy, sz, sA, sB;
            ADD2(dx, px2[j], ncx2);
            ADD2(dy, py2[j], ncy2);
            ADD2(dz, pz2[j], ncz2);
            MUL2(sx, dx, dx);
            MUL2(sy, dy, dy);
            MUL2(sz, dz, dz);
            ADD2(sA, sx, sy);        // (dx^2 + dy^2)
            ADD2(sB, sA, sz);        // + dz^2 — exact reference fold per lane
            float d0, d1; UNPACK2(d0, d1, sB);
            float nd0 = fminf(dd[2*j], d0);   dd[2*j]   = nd0;
            if (nd0 > bv) { bv = nd0; bi = t + (2*j)*512; }     // strict > keeps lowest idx
            float nd1 = fminf(dd[2*j+1], d1); dd[2*j+1] = nd1;
            if (nd1 > bv) { bv = nd1; bi = t + (2*j+1)*512; }
        }
        unsigned long long key = ((unsigned long long)__float_as_uint(bv) << 32)
                               | (unsigned)(~(unsigned)bi);
        #pragma unroll
        for (int off = 16; off; off >>= 1) {
            unsigned long long o = __shfl_down_sync(0xffffffffu, key, off);
            if (o > key) key = o;
        }
        const int par = i & 1;
        if (lane == 0) swk[par][wid] = key;
        __syncthreads();
        unsigned long long k2 = swk[par][lane & 15];
        #pragma unroll
        for (int off = 8; off; off >>= 1) {
            unsigned long long o = __shfl_xor_sync(0xffffffffu, k2, off);
            if (o > k2) k2 = o;
        }
        far = (int)(~(unsigned)k2);
    }
}

// ---------------- ball query: 4 queries/block, 256 threads, flattened rank ----------------
__global__ void __launch_bounds__(BT) k_ball(const float* __restrict__ xyz) {
    const int blk = blockIdx.x;
    const int q0 = blk * QPB;
    const int b = q0 >> 10;
    const int t = threadIdx.x;
    __shared__ unsigned long long ck[QPB][CAP];
    __shared__ int scnt[QPB];
    __shared__ int sm_m[QPB];
    __shared__ int soff[QPB+1];
    __shared__ int ssel[QPB][Kq];
    if (t < QPB) scnt[t] = 0;
    __syncthreads();
    float cx[QPB], cy[QPB], cz[QPB], sa[QPB];
    #pragma unroll
    for (int j = 0; j < QPB; j++) {
        cx[j] = g_newxyz[3*(q0+j)]; cy[j] = g_newxyz[3*(q0+j)+1]; cz[j] = g_newxyz[3*(q0+j)+2];
        sa[j] = __fadd_rn(__fadd_rn(__fmul_rn(cx[j],cx[j]), __fmul_rn(cy[j],cy[j])), __fmul_rn(cz[j],cz[j]));
    }
    const float* xb = xyz + b*Nq*3;
    const float* sq = g_sqn + b*Nq;
    for (int n = t; n < Nq; n += BT) {
        float x = xb[3*n], y = xb[3*n+1], z = xb[3*n+2];
        float sn = sq[n];
        #pragma unroll
        for (int j = 0; j < QPB; j++) {
            float dot = __fadd_rn(__fadd_rn(__fmul_rn(x,cx[j]), __fmul_rn(y,cy[j])), __fmul_rn(z,cz[j]));
            float d = __fsub_rn(__fadd_rn(sa[j], sn), __fmul_rn(2.0f, dot));
            if (d <= 0.04f) {
                unsigned ub = __float_as_uint(d);
                ub = ((int)ub < 0) ? ~ub : (ub | 0x80000000u);   // monotone float->uint
                int p = atomicAdd(&scnt[j], 1);
                if (p < CAP) ck[j][p] = ((unsigned long long)ub << 32) | (unsigned)n;
            }
        }
    }
    __syncthreads();
    if (t == 0) {
        int acc = 0;
        #pragma unroll
        for (int j = 0; j < QPB; j++) {
            soff[j] = acc;
            int c = scnt[j] < CAP ? scnt[j] : CAP;
            sm_m[j] = c < Kq ? c : Kq;
            acc += c;
        }
        soff[QPB] = acc;
    }
    __syncthreads();
    // flattened (query, candidate) ranking: balances ~548 rank loops over all 256 threads
    const int total = soff[QPB];
    for (int w = t; w < total; w += BT) {
        int j = 0;
        #pragma unroll
        for (int jj = 1; jj < QPB; jj++) j += (w >= soff[jj]);
        int p = w - soff[j];
        int cnt = soff[j+1] - soff[j];
        unsigned long long mk = ck[j][p];
        int r = 0;
        for (int i = 0; i < cnt; i++) r += (ck[j][i] < mk);
        if (r < Kq) ssel[j][r] = (int)(unsigned)mk;
    }
    __syncthreads();
    if (t < QPB*Kq) {
        int j = t >> 5, k = t & 31;
        g_grp[(q0+j)*Kq + k] = ssel[j][k < sm_m[j] ? k : 0];
    }
}

// ---------------- point-feature GEMM (FFMA2 mainloop, R7) ----------------
__global__ void __launch_bounds__(128) k_pf(const float* __restrict__ points,
                                            const float* __restrict__ W0) {
    extern __shared__ float sm[];
    float* xs = sm;                   // [64][XS_PAD]
    float* Wt = sm + 64*XS_PAD;       // [64][64]
    const int t = threadIdx.x;
    const int blk = blockIdx.x;
    for (int i = t; i < 4096; i += 128) Wt[i] = W0[(i & 63)*67 + 3 + (i >> 6)];
    const float4* pts4 = (const float4*)points;
    #pragma unroll
    for (int jj = 0; jj < 16; jj++) {
        int idx = t + jj*128;
        int r = idx >> 4, c4 = idx & 15;
        float4 v = pts4[(size_t)(blk*128 + r)*16 + c4];
        xs[(4*c4+0)*XS_PAD + r] = v.x;
        xs[(4*c4+1)*XS_PAD + r] = v.y;
        xs[(4*c4+2)*XS_PAD + r] = v.z;
        xs[(4*c4+3)*XS_PAD + r] = v.w;
    }
    __syncthreads();
    const int r0 = (t & 15)*8, o0 = (t >> 4)*8;
    unsigned long long acc2[8][4];
    #pragma unroll
    for (int i = 0; i < 8; i++)
        #pragma unroll
        for (int j = 0; j < 4; j++) acc2[i][j] = 0ull;
    for (int c = 0; c < 64; c++) {
        float4 xa = *(const float4*)&xs[c*XS_PAD + r0];
        float4 xc = *(const float4*)&xs[c*XS_PAD + r0 + 4];
        ulonglong2 wA = *(const ulonglong2*)&Wt[c*64 + o0];
        ulonglong2 wB = *(const ulonglong2*)&Wt[c*64 + o0 + 4];
        unsigned long long wp[4] = {wA.x, wA.y, wB.x, wB.y};
        float xr[8] = {xa.x,xa.y,xa.z,xa.w,xc.x,xc.y,xc.z,xc.w};
        unsigned long long xp[8];
        #pragma unroll
        for (int i = 0; i < 8; i++) PACK2(xp[i], xr[i], xr[i]);
        #pragma unroll
        for (int i = 0; i < 8; i++)
            #pragma unroll
            for (int j = 0; j < 4; j++) FMA2(acc2[i][j], xp[i], wp[j]);
    }
    #pragma unroll
    for (int i = 0; i < 8; i++) {
        size_t base = ((size_t)(blk*128 + r0 + i))*64 + o0;
        *(ulonglong2*)&g_pf[base]   = make_ulonglong2(acc2[i][0], acc2[i][1]);
        *(ulonglong2*)&g_pf[base+4] = make_ulonglong2(acc2[i][2], acc2[i][3]);
    }
}

// ---------------- layer0 stats: vectorized gather (LDG.128, warp-coalesced rows) ----------------
__global__ void __launch_bounds__(256) k_l0stats(const float* __restrict__ xyz,
                                                 const float* __restrict__ W0,
                                                 const float* __restrict__ b0) {
    __shared__ int   sgp[256];
    __shared__ float sdx[256], sdy[256], sdz[256];
    __shared__ float swx[64], swy[64], swz[64], sb[64];
    __shared__ float ps[64][17], pq[64][17];
    const int t = threadIdx.x;
    const int blk = blockIdx.x;
    if (t < 64) {
        swx[t] = W0[t*67+0]; swy[t] = W0[t*67+1]; swz[t] = W0[t*67+2]; sb[t] = b0[t];
    }
    {
        int R = blk*256 + t;
        int q = R >> 5, b = q >> 10;
        int gp = b*Nq + g_grp[R];
        sgp[t] = gp;
        sdx[t] = __fsub_rn(xyz[gp*3+0], g_newxyz[3*q+0]);
        sdy[t] = __fsub_rn(xyz[gp*3+1], g_newxyz[3*q+1]);
        sdz[t] = __fsub_rn(xyz[gp*3+2], g_newxyz[3*q+2]);
    }
    __syncthreads();
    const int cg = t & 15, rg = t >> 4;
    const int c0 = cg*4;
    float wx[4], wy[4], wz[4], bb[4];
    #pragma unroll
    for (int k = 0; k < 4; k++) { wx[k]=swx[c0+k]; wy[k]=swy[c0+k]; wz[k]=swz[c0+k]; bb[k]=sb[c0+k]; }
    float s[4] = {0,0,0,0}, s2[4] = {0,0,0,0};
    const float4* pf4 = (const float4*)g_pf;
    #pragma unroll 4
    for (int rr = 0; rr < 16; rr++) {
        int r = rg*16 + rr;
        float4 p = pf4[(size_t)sgp[r]*16 + cg];
        float dx = sdx[r], dy = sdy[r], dz = sdz[r];
        float pv[4] = {p.x, p.y, p.z, p.w};
        #pragma unroll
        for (int k = 0; k < 4; k++) {
            float y = pv[k] + fmaf(dx, wx[k], fmaf(dy, wy[k], fmaf(dz, wz[k], bb[k])));
            s[k] += y; s2[k] = fmaf(y, y, s2[k]);
        }
    }
    #pragma unroll
    for (int k = 0; k < 4; k++) { ps[c0+k][rg] = s[k]; pq[c0+k][rg] = s2[k]; }
    __syncthreads();
    if (t < 64) {
        double S = 0.0, Q = 0.0;
        #pragma unroll
        for (int g = 0; g < 16; g++) { S += (double)ps[t][g]; Q += (double)pq[t][g]; }
        g_part[(size_t)t*8192 + blk]       = S;
        g_part[(size_t)(128+t)*8192 + blk] = Q;
    }
}

// ---------------- BN finalize ----------------
__global__ void __launch_bounds__(256) k_fin(const float* __restrict__ ga,
                                             const float* __restrict__ be,
                                             int off, int nblk) {
    const int ch = blockIdx.x;
    const int t = threadIdx.x;
    double s = 0.0, s2 = 0.0;
    const double* p0 = g_part + (size_t)ch*8192;
    const double* p1 = g_part + (size_t)(128+ch)*8192;
    for (int i = t; i < nblk; i += 256) { s += p0[i]; s2 += p1[i]; }
    __shared__ double sh[256], sh2[256];
    sh[t] = s; sh2[t] = s2; __syncthreads();
    for (int o = 128; o; o >>= 1) {
        if (t < o) { sh[t] += sh[t+o]; sh2[t] += sh2[t+o]; }
        __syncthreads();
    }
    if (t == 0) {
        double mu  = sh[0]  / (double)NEq;
        double var = sh2[0] / (double)NEq - mu*mu;
        if (var < 0.0) var = 0.0;
        double sc = (double)ga[ch] / sqrt(var + 1e-5);
        g_scale[off+ch] = (float)sc;
        g_shift[off+ch] = (float)((double)be[ch] - mu*sc);
    }
}

// ---------------- layer1 (FFMA2 + lazy epilogue, R7) ----------------
__global__ void __launch_bounds__(128) k_layer1(const float* __restrict__ xyz,
                                                const float* __restrict__ W0,
                                                const float* __restrict__ b0,
                                                const float* __restrict__ W1,
                                                const float* __restrict__ b1) {
    extern __shared__ float sm[];
    float* xs  = sm;                   // [64][XS_PAD]
    float* Wt  = sm + 64*XS_PAD;       // [64][64]
    float* swx = Wt + 4096;
    float* swy = swx + 64; float* swz = swy + 64; float* sb = swz + 64;
    float* ssc = sb + 64;  float* ssh = ssc + 64;
    const int t = threadIdx.x;
    const int blk = blockIdx.x;
    for (int i = t; i < 4096; i += 128) Wt[i] = W1[(i & 63)*64 + (i >> 6)];
    if (t < 64) {
        swx[t] = W0[t*67+0]; swy[t] = W0[t*67+1]; swz[t] = W0[t*67+2];
        sb[t] = b0[t]; ssc[t] = g_scale[t]; ssh[t] = g_shift[t];
    }
    int R = blk*128 + t;
    int q = R >> 5, b = q >> 10;
    int gp = b*Nq + g_grp[R];
    float dx = __fsub_rn(xyz[gp*3+0], g_newxyz[3*q+0]);
    float dy = __fsub_rn(xyz[gp*3+1], g_newxyz[3*q+1]);
    float dz = __fsub_rn(xyz[gp*3+2], g_newxyz[3*q+2]);
    __syncthreads();
    const float4* pfv4 = (const float4*)g_pf;
    #pragma unroll
    for (int c4 = 0; c4 < 16; c4++) {
        float4 p = pfv4[(size_t)gp*16 + c4];
        float pv[4] = {p.x, p.y, p.z, p.w};
        #pragma unroll
        for (int k2 = 0; k2 < 4; k2++) {
            int c = c4*4 + k2;
            float y = pv[k2] + fmaf(dx, swx[c], fmaf(dy, swy[c], fmaf(dz, swz[c], sb[c])));
            xs[c*XS_PAD + t] = fmaxf(fmaf(ssc[c], y, ssh[c]), 0.0f);
        }
    }
    __syncthreads();
    const int r0 = (t & 15)*8, o0 = (t >> 4)*8;
    unsigned long long acc2[8][4];
    {
        ulonglong2 bA = *(const ulonglong2*)&b1[o0];
        ulonglong2 bB = *(const ulonglong2*)&b1[o0+4];
        unsigned long long bp[4] = {bA.x, bA.y, bB.x, bB.y};
        #pragma unroll
        for (int i = 0; i < 8; i++)
            #pragma unroll
            for (int j = 0; j < 4; j++) acc2[i][j] = bp[j];
    }
    for (int c = 0; c < 64; c++) {
        float4 xa = *(const float4*)&xs[c*XS_PAD + r0];
        float4 xc = *(const float4*)&xs[c*XS_PAD + r0 + 4];
        ulonglong2 wA = *(const ulonglong2*)&Wt[c*64 + o0];
        ulonglong2 wB = *(const ulonglong2*)&Wt[c*64 + o0 + 4];
        unsigned long long wp[4] = {wA.x, wA.y, wB.x, wB.y};
        float xr[8] = {xa.x,xa.y,xa.z,xa.w,xc.x,xc.y,xc.z,xc.w};
        unsigned long long xp[8];
        #pragma unroll
        for (int i = 0; i < 8; i++) PACK2(xp[i], xr[i], xr[i]);
        #pragma unroll
        for (int i = 0; i < 8; i++)
            #pragma unroll
            for (int j = 0; j < 4; j++) FMA2(acc2[i][j], xp[i], wp[j]);
    }
    #pragma unroll
    for (int i = 0; i < 8; i++) {
        size_t base = ((size_t)(blk*128 + r0 + i))*64 + o0;
        *(ulonglong2*)&g_y1[base]   = make_ulonglong2(acc2[i][0], acc2[i][1]);
        *(ulonglong2*)&g_y1[base+4] = make_ulonglong2(acc2[i][2], acc2[i][3]);
    }
    #pragma unroll
    for (int jp = 0; jp < 4; jp++) {
        float s0 = 0.0f, q0s = 0.0f, s1 = 0.0f, q1s = 0.0f;
        #pragma unroll
        for (int i = 0; i < 8; i++) {
            float a0, a1; UNPACK2(a0, a1, acc2[i][jp]);
            s0 += a0; q0s = fmaf(a0, a0, q0s);
            s1 += a1; q1s = fmaf(a1, a1, q1s);
        }
        #pragma unroll
        for (int off = 8; off; off >>= 1) {
            s0  += __shfl_down_sync(0xffffffffu, s0,  off, 16);
            q0s += __shfl_down_sync(0xffffffffu, q0s, off, 16);
            s1  += __shfl_down_sync(0xffffffffu, s1,  off, 16);
            q1s += __shfl_down_sync(0xffffffffu, q1s, off, 16);
        }
        if ((t & 15) == 0) {
            g_part[(size_t)(o0+2*jp)*8192 + blk]       = (double)s0;
            g_part[(size_t)(128+o0+2*jp)*8192 + blk]   = (double)q0s;
            g_part[(size_t)(o0+2*jp+1)*8192 + blk]     = (double)s1;
            g_part[(size_t)(128+o0+2*jp+1)*8192 + blk] = (double)q1s;
        }
    }
}

// ---------------- layer2 (FFMA2 + lazy epilogue, R7) ----------------
__global__ void __launch_bounds__(256, 2) k_layer2(const float* __restrict__ W2,
                                                   const float* __restrict__ b2) {
    extern __shared__ float sm[];
    float* xs  = sm;                   // [64][XS_PAD]
    float* Wt  = sm + 64*XS_PAD;       // [64][128]
    float* ssc = Wt + 8192;
    float* ssh = ssc + 64;
    const int t = threadIdx.x;
    const int blk = blockIdx.x;
    for (int i = t; i < 8192; i += 256) Wt[i] = W2[(i & 127)*64 + (i >> 7)];
    if (t < 64) { ssc[t] = g_scale[128+t]; ssh[t] = g_shift[128+t]; }
    __syncthreads();
    const float4* y1v = (const float4*)g_y1;
    #pragma unroll
    for (int jj = 0; jj < 8; jj++) {
        int idx = t + jj*256;
        int r = idx >> 4, c4 = idx & 15;
        float4 v = y1v[(size_t)(blk*128 + r)*16 + c4];
        float pv[4] = {v.x, v.y, v.z, v.w};
        #pragma unroll
        for (int k2 = 0; k2 < 4; k2++) {
            int c = c4*4 + k2;
            xs[c*XS_PAD + r] = fmaxf(fmaf(ssc[c], pv[k2], ssh[c]), 0.0f);
        }
    }
    __syncthreads();
    const int r0 = (t & 15)*8, o0 = (t >> 4)*8;
    unsigned long long acc2[8][4];
    {
        ulonglong2 bA = *(const ulonglong2*)&b2[o0];
        ulonglong2 bB = *(const ulonglong2*)&b2[o0+4];
        unsigned long long bp[4] = {bA.x, bA.y, bB.x, bB.y};
        #pragma unroll
        for (int i = 0; i < 8; i++)
            #pragma unroll
            for (int j = 0; j < 4; j++) acc2[i][j] = bp[j];
    }
    for (int c = 0; c < 64; c++) {
        float4 xa = *(const float4*)&xs[c*XS_PAD + r0];
        float4 xc = *(const float4*)&xs[c*XS_PAD + r0 + 4];
        ulonglong2 wA = *(const ulonglong2*)&Wt[c*128 + o0];
        ulonglong2 wB = *(const ulonglong2*)&Wt[c*128 + o0 + 4];
        unsigned long long wp[4] = {wA.x, wA.y, wB.x, wB.y};
        float xr[8] = {xa.x,xa.y,xa.z,xa.w,xc.x,xc.y,xc.z,xc.w};
        unsigned long long xp[8];
        #pragma unroll
        for (int i = 0; i < 8; i++) PACK2(xp[i], xr[i], xr[i]);
        #pragma unroll
        for (int i = 0; i < 8; i++)
            #pragma unroll
            for (int j = 0; j < 4; j++) FMA2(acc2[i][j], xp[i], wp[j]);
    }
    #pragma unroll
    for (int jp = 0; jp < 4; jp++) {
        float a0, a1; UNPACK2(a0, a1, acc2[0][jp]);
        float s0 = a0, q0s = a0*a0, mx0 = a0, mn0 = a0;
        float s1 = a1, q1s = a1*a1, mx1 = a1, mn1 = a1;
        #pragma unroll
        for (int i = 1; i < 8; i++) {
            UNPACK2(a0, a1, acc2[i][jp]);
            s0 += a0; q0s = fmaf(a0, a0, q0s); mx0 = fmaxf(mx0, a0); mn0 = fminf(mn0, a0);
            s1 += a1; q1s = fmaf(a1, a1, q1s); mx1 = fmaxf(mx1, a1); mn1 = fminf(mn1, a1);
        }
        #pragma unroll
        for (int off = 8; off; off >>= 1) {
            s0  += __shfl_down_sync(0xffffffffu, s0,  off, 16);
            q0s += __shfl_down_sync(0xffffffffu, q0s, off, 16);
            s1  += __shfl_down_sync(0xffffffffu, s1,  off, 16);
            q1s += __shfl_down_sync(0xffffffffu, q1s, off, 16);
        }
        if ((t & 15) == 0) {
            g_part[(size_t)(o0+2*jp)*8192 + blk]       = (double)s0;
            g_part[(size_t)(128+o0+2*jp)*8192 + blk]   = (double)q0s;
            g_part[(size_t)(o0+2*jp+1)*8192 + blk]     = (double)s1;
            g_part[(size_t)(128+o0+2*jp+1)*8192 + blk] = (double)q1s;
        }
        #pragma unroll
        for (int off = 2; off; off >>= 1) {
            mx0 = fmaxf(mx0, __shfl_down_sync(0xffffffffu, mx0, off, 4));
            mn0 = fminf(mn0, __shfl_down_sync(0xffffffffu, mn0, off, 4));
            mx1 = fmaxf(mx1, __shfl_down_sync(0xffffffffu, mx1, off, 4));
            mn1 = fminf(mn1, __shfl_down_sync(0xffffffffu, mn1, off, 4));
        }
        if ((t & 3) == 0) {
            int qg = blk*4 + ((t & 15) >> 2);
            g_maxv[(size_t)qg*128 + o0 + 2*jp]     = mx0;
            g_minv[(size_t)qg*128 + o0 + 2*jp]     = mn0;
            g_maxv[(size_t)qg*128 + o0 + 2*jp + 1] = mx1;
            g_minv[(size_t)qg*128 + o0 + 2*jp + 1] = mn1;
        }
    }
}

// ---------------- final: BN2+ReLU fused max-pool from min/max ----------------
__global__ void __launch_bounds__(256) k_maxpool(float* __restrict__ out) {
    int i = blockIdx.x*256 + threadIdx.x;
    int o = i & 127;
    float sc = g_scale[256+o], sh = g_shift[256+o];
    float v = (sc >= 0.0f) ? g_maxv[i] : g_minv[i];
    out[OUT_PTS + i] = fmaxf(fmaf(sc, v, sh), 0.0f);
}

// ---------------- launch (sequential, R10 skeleton — no fork) ----------------
extern "C" void kernel_launch(void* const* d_in, const int* in_sizes, int n_in,
                              void* d_out, int out_size) {
    (void)in_sizes; (void)n_in; (void)out_size;
    const float* xyz    = (const float*)d_in[0];
    const float* points = (const float*)d_in[1];
    const float* W0  = (const float*)d_in[2];
    const float* b0  = (const float*)d_in[3];
    const float* g0  = (const float*)d_in[4];
    const float* bt0 = (const float*)d_in[5];
    const float* W1  = (const float*)d_in[6];
    const float* b1  = (const float*)d_in[7];
    const float* g1  = (const float*)d_in[8];
    const float* bt1 = (const float*)d_in[9];
    const float* W2  = (const float*)d_in[10];
    const float* b2  = (const float*)d_in[11];
    const float* g2  = (const float*)d_in[12];
    const float* bt2 = (const float*)d_in[13];
    float* out = (float*)d_out;

    const int SM_PF = (64*XS_PAD + 64*64) * 4;
    const int SM_L1 = (64*XS_PAD + 64*64 + 6*64) * 4;
    const int SM_L2 = (64*XS_PAD + 64*128 + 2*64) * 4;
    cudaFuncSetAttribute(k_pf,     cudaFuncAttributeMaxDynamicSharedMemorySize, SM_PF);
    cudaFuncSetAttribute(k_layer1, cudaFuncAttributeMaxDynamicSharedMemorySize, SM_L1);
    cudaFuncSetAttribute(k_layer2, cudaFuncAttributeMaxDynamicSharedMemorySize, SM_L2);

    k_prep<<<(NP + 255)/256, 256>>>(xyz);
    k_pf<<<NP/128, 128, SM_PF>>>(points, W0);
    k_fps<<<Bq, 512>>>(xyz, out);
    k_ball<<<NQ/QPB, BT>>>(xyz);

    k_l0stats<<<NEq/256, 256>>>(xyz, W0, b0);
    k_fin<<<64, 256>>>(g0, bt0, 0, NEq/256);
    k_layer1<<<NEq/128, 128, SM_L1>>>(xyz, W0, b0, W1, b1);
    k_fin<<<64, 256>>>(g1, bt1, 128, NEq/128);
    k_layer2<<<NEq/128, 256, SM_L2>>>(W2, b2);
    k_fin<<<128, 256>>>(g2, bt2, 256, NEq/128);
    k_maxpool<<<NQ*128/256, 256>>>(out);
}

// round 13
// speedup vs baseline: 1.0213x; 1.0115x over previous
#include <cuda_runtime.h>
#include <cstdint>

#define Bq 16
#define Nq 4096
#define Sq 1024
#define Kq 32
#define NQ (Bq*Sq)          // 16384 queries
#define NP (Bq*Nq)          // 65536 points
#define NEq (NQ*Kq)         // 524288 rows
#define OUT_PTS (NQ*3)
#define XS_PAD 132
#define QPB 4               // queries per ball block
#define CAP 768             // candidate cap per query (mean 137, sd ~12)
#define BT 256              // ball block threads

// packed fp32x2 helpers (exact IEEE fp32 per lane; only add/mul/fma exist packed)
#define FMA2(d,a,b)   asm("fma.rn.f32x2 %0, %1, %2, %0;" : "+l"(d) : "l"(a), "l"(b))
#define ADD2(d,a,b)   asm("add.rn.f32x2 %0, %1, %2;" : "=l"(d) : "l"(a), "l"(b))
#define MUL2(d,a,b)   asm("mul.rn.f32x2 %0, %1, %2;" : "=l"(d) : "l"(a), "l"(b))
#define PACK2(d,x,y)  asm("mov.b64 %0, {%1, %2};" : "=l"(d) : "f"(x), "f"(y))
#define UNPACK2(x,y,d) asm("mov.b64 {%0, %1}, %2;" : "=f"(x), "=f"(y) : "l"(d))

// ---------------- scratch ----------------
__device__ float  g_newxyz[NQ*3];
__device__ int    g_grp[NEq];
__device__ float  g_pf[(size_t)NP*64];        // point features (layer0 w/o geom), 16MB
__device__ float  g_y1[(size_t)NEq*64];       // layer1 pre-BN output, 134MB
__device__ float  g_maxv[(size_t)NQ*128];
__device__ float  g_minv[(size_t)NQ*128];
__device__ double g_part[(size_t)256*8192];
__device__ float  g_scale[384];
__device__ float  g_shift[384];

// ---------------- FPS: smem xyz cache, packed f32x2 body, R10 tail ----------------
__global__ void __launch_bounds__(512) k_fps(const float* __restrict__ xyz,
                                             float* __restrict__ out) {
    const int b = blockIdx.x;
    const int t = threadIdx.x;
    const int lane = t & 31, wid = t >> 5;
    const float* xb = xyz + b*Nq*3;
    __shared__ float sxy[Nq*3];                 // 48KB: whole batch resident in smem
    __shared__ unsigned long long swk[2][16];   // double-buffered warp partials
    {
        const float4* src = (const float4*)xb;
        float4* dst = (float4*)sxy;
        #pragma unroll
        for (int i = 0; i < (Nq*3/4)/512; i++) dst[t + i*512] = src[t + i*512];
    }
    __syncthreads();
    // pair j: points p0 = t + 2j*512 (lane0) and p1 = p0 + 512 (lane1); p0 < p1
    unsigned long long px2[4], py2[4], pz2[4];
    float dd[8];
    #pragma unroll
    for (int j = 0; j < 4; j++) {
        int p0 = t + (2*j)*512, p1 = p0 + 512;
        PACK2(px2[j], sxy[3*p0],   sxy[3*p1]);
        PACK2(py2[j], sxy[3*p0+1], sxy[3*p1+1]);
        PACK2(pz2[j], sxy[3*p0+2], sxy[3*p1+2]);
        dd[2*j] = 1e10f; dd[2*j+1] = 1e10f;
    }
    int far = 0;
    for (int i = 0; i < Sq; i++) {
        float cx = sxy[3*far], cy = sxy[3*far+1], cz = sxy[3*far+2];
        if (t == 0) {
            int o = (b*Sq + i)*3;
            g_newxyz[o] = cx; g_newxyz[o+1] = cy; g_newxyz[o+2] = cz;
            out[o] = cx; out[o+1] = cy; out[o+2] = cz;
        }
        float ncx = -cx, ncy = -cy, ncz = -cz;   // x - c == x + (-c) exactly
        unsigned long long ncx2, ncy2, ncz2;
        PACK2(ncx2, ncx, ncx); PACK2(ncy2, ncy, ncy); PACK2(ncz2, ncz, ncz);
        float bv = -1.0f; int bi = 0;
        #pragma unroll
        for (int j = 0; j < 4; j++) {
            unsigned long long dx, dy, dz, sx, sy, sz, sA, sB;
            ADD2(dx, px2[j], ncx2);
            ADD2(dy, py2[j], ncy2);
            ADD2(dz, pz2[j], ncz2);
            MUL2(sx, dx, dx);
            MUL2(sy, dy, dy);
            MUL2(sz, dz, dz);
            ADD2(sA, sx, sy);        // (dx^2 + dy^2)
            ADD2(sB, sA, sz);        // + dz^2 — exact reference fold per lane
            float d0, d1; UNPACK2(d0, d1, sB);
            float nd0 = fminf(dd[2*j], d0);   dd[2*j]   = nd0;
            if (nd0 > bv) { bv = nd0; bi = t + (2*j)*512; }     // strict > keeps lowest idx
            float nd1 = fminf(dd[2*j+1], d1); dd[2*j+1] = nd1;
            if (nd1 > bv) { bv = nd1; bi = t + (2*j+1)*512; }
        }
        unsigned long long key = ((unsigned long long)__float_as_uint(bv) << 32)
                               | (unsigned)(~(unsigned)bi);
        #pragma unroll
        for (int off = 16; off; off >>= 1) {
            unsigned long long o = __shfl_down_sync(0xffffffffu, key, off);
            if (o > key) key = o;
        }
        const int par = i & 1;
        if (lane == 0) swk[par][wid] = key;
        __syncthreads();
        unsigned long long k2 = swk[par][lane & 15];
        #pragma unroll
        for (int off = 8; off; off >>= 1) {
            unsigned long long o = __shfl_xor_sync(0xffffffffu, k2, off);
            if (o > k2) k2 = o;
        }
        far = (int)(~(unsigned)k2);
    }
}

// ---------------- ball query: vectorized sweep (3xLDG.128 per 4 pts), inline |p|^2 ----------------
__global__ void __launch_bounds__(BT) k_ball(const float* __restrict__ xyz) {
    const int blk = blockIdx.x;
    const int q0 = blk * QPB;
    const int b = q0 >> 10;
    const int t = threadIdx.x;
    __shared__ unsigned long long ck[QPB][CAP];
    __shared__ int scnt[QPB];
    __shared__ int sm_m[QPB];
    __shared__ int soff[QPB+1];
    __shared__ int ssel[QPB][Kq];
    if (t < QPB) scnt[t] = 0;
    __syncthreads();
    float cx[QPB], cy[QPB], cz[QPB], sa[QPB];
    #pragma unroll
    for (int j = 0; j < QPB; j++) {
        cx[j] = g_newxyz[3*(q0+j)]; cy[j] = g_newxyz[3*(q0+j)+1]; cz[j] = g_newxyz[3*(q0+j)+2];
        sa[j] = __fadd_rn(__fadd_rn(__fmul_rn(cx[j],cx[j]), __fmul_rn(cy[j],cy[j])), __fmul_rn(cz[j],cz[j]));
    }
    const float4* xb4 = (const float4*)(xyz + (size_t)b*Nq*3);   // batch base is 16B-aligned
    #pragma unroll
    for (int k = 0; k < Nq/(4*BT); k++) {
        int m = t + k*BT;                       // 4-point group
        float4 f0 = xb4[3*m], f1 = xb4[3*m+1], f2 = xb4[3*m+2];
        float gx[4] = {f0.x, f0.w, f1.z, f2.y};
        float gy[4] = {f0.y, f1.x, f1.w, f2.z};
        float gz[4] = {f0.z, f1.y, f2.x, f2.w};
        #pragma unroll
        for (int u = 0; u < 4; u++) {
            int n = 4*m + u;
            float x = gx[u], y = gy[u], z = gz[u];
            float sn = __fadd_rn(__fadd_rn(__fmul_rn(x,x), __fmul_rn(y,y)), __fmul_rn(z,z));
            #pragma unroll
            for (int j = 0; j < QPB; j++) {
                float dot = __fadd_rn(__fadd_rn(__fmul_rn(x,cx[j]), __fmul_rn(y,cy[j])), __fmul_rn(z,cz[j]));
                float d = __fsub_rn(__fadd_rn(sa[j], sn), __fmul_rn(2.0f, dot));
                if (d <= 0.04f) {
                    unsigned ub = __float_as_uint(d);
                    ub = ((int)ub < 0) ? ~ub : (ub | 0x80000000u);   // monotone float->uint
                    int p = atomicAdd(&scnt[j], 1);
                    if (p < CAP) ck[j][p] = ((unsigned long long)ub << 32) | (unsigned)n;
                }
            }
        }
    }
    __syncthreads();
    if (t == 0) {
        int acc = 0;
        #pragma unroll
        for (int j = 0; j < QPB; j++) {
            soff[j] = acc;
            int c = scnt[j] < CAP ? scnt[j] : CAP;
            sm_m[j] = c < Kq ? c : Kq;
            acc += c;
        }
        soff[QPB] = acc;
    }
    __syncthreads();
    // flattened (query, candidate) ranking
    const int total = soff[QPB];
    for (int w = t; w < total; w += BT) {
        int j = 0;
        #pragma unroll
        for (int jj = 1; jj < QPB; jj++) j += (w >= soff[jj]);
        int p = w - soff[j];
        int cnt = soff[j+1] - soff[j];
        unsigned long long mk = ck[j][p];
        int r = 0;
        for (int i = 0; i < cnt; i++) r += (ck[j][i] < mk);
        if (r < Kq) ssel[j][r] = (int)(unsigned)mk;
    }
    __syncthreads();
    if (t < QPB*Kq) {
        int j = t >> 5, k = t & 31;
        g_grp[(q0+j)*Kq + k] = ssel[j][k < sm_m[j] ? k : 0];
    }
}

// ---------------- point-feature GEMM (FFMA2 mainloop, R7) ----------------
__global__ void __launch_bounds__(128) k_pf(const float* __restrict__ points,
                                            const float* __restrict__ W0) {
    extern __shared__ float sm[];
    float* xs = sm;                   // [64][XS_PAD]
    float* Wt = sm + 64*XS_PAD;       // [64][64]
    const int t = threadIdx.x;
    const int blk = blockIdx.x;
    for (int i = t; i < 4096; i += 128) Wt[i] = W0[(i & 63)*67 + 3 + (i >> 6)];
    const float4* pts4 = (const float4*)points;
    #pragma unroll
    for (int jj = 0; jj < 16; jj++) {
        int idx = t + jj*128;
        int r = idx >> 4, c4 = idx & 15;
        float4 v = pts4[(size_t)(blk*128 + r)*16 + c4];
        xs[(4*c4+0)*XS_PAD + r] = v.x;
        xs[(4*c4+1)*XS_PAD + r] = v.y;
        xs[(4*c4+2)*XS_PAD + r] = v.z;
        xs[(4*c4+3)*XS_PAD + r] = v.w;
    }
    __syncthreads();
    const int r0 = (t & 15)*8, o0 = (t >> 4)*8;
    unsigned long long acc2[8][4];
    #pragma unroll
    for (int i = 0; i < 8; i++)
        #pragma unroll
        for (int j = 0; j < 4; j++) acc2[i][j] = 0ull;
    for (int c = 0; c < 64; c++) {
        float4 xa = *(const float4*)&xs[c*XS_PAD + r0];
        float4 xc = *(const float4*)&xs[c*XS_PAD + r0 + 4];
        ulonglong2 wA = *(const ulonglong2*)&Wt[c*64 + o0];
        ulonglong2 wB = *(const ulonglong2*)&Wt[c*64 + o0 + 4];
        unsigned long long wp[4] = {wA.x, wA.y, wB.x, wB.y};
        float xr[8] = {xa.x,xa.y,xa.z,xa.w,xc.x,xc.y,xc.z,xc.w};
        unsigned long long xp[8];
        #pragma unroll
        for (int i = 0; i < 8; i++) PACK2(xp[i], xr[i], xr[i]);
        #pragma unroll
        for (int i = 0; i < 8; i++)
            #pragma unroll
            for (int j = 0; j < 4; j++) FMA2(acc2[i][j], xp[i], wp[j]);
    }
    #pragma unroll
    for (int i = 0; i < 8; i++) {
        size_t base = ((size_t)(blk*128 + r0 + i))*64 + o0;
        *(ulonglong2*)&g_pf[base]   = make_ulonglong2(acc2[i][0], acc2[i][1]);
        *(ulonglong2*)&g_pf[base+4] = make_ulonglong2(acc2[i][2], acc2[i][3]);
    }
}

// ---------------- layer0 stats: vectorized gather (LDG.128, warp-coalesced rows) ----------------
__global__ void __launch_bounds__(256) k_l0stats(const float* __restrict__ xyz,
                                                 const float* __restrict__ W0,
                                                 const float* __restrict__ b0) {
    __shared__ int   sgp[256];
    __shared__ float sdx[256], sdy[256], sdz[256];
    __shared__ float swx[64], swy[64], swz[64], sb[64];
    __shared__ float ps[64][17], pq[64][17];
    const int t = threadIdx.x;
    const int blk = blockIdx.x;
    if (t < 64) {
        swx[t] = W0[t*67+0]; swy[t] = W0[t*67+1]; swz[t] = W0[t*67+2]; sb[t] = b0[t];
    }
    {
        int R = blk*256 + t;
        int q = R >> 5, b = q >> 10;
        int gp = b*Nq + g_grp[R];
        sgp[t] = gp;
        sdx[t] = __fsub_rn(xyz[gp*3+0], g_newxyz[3*q+0]);
        sdy[t] = __fsub_rn(xyz[gp*3+1], g_newxyz[3*q+1]);
        sdz[t] = __fsub_rn(xyz[gp*3+2], g_newxyz[3*q+2]);
    }
    __syncthreads();
    const int cg = t & 15, rg = t >> 4;
    const int c0 = cg*4;
    float wx[4], wy[4], wz[4], bb[4];
    #pragma unroll
    for (int k = 0; k < 4; k++) { wx[k]=swx[c0+k]; wy[k]=swy[c0+k]; wz[k]=swz[c0+k]; bb[k]=sb[c0+k]; }
    float s[4] = {0,0,0,0}, s2[4] = {0,0,0,0};
    const float4* pf4 = (const float4*)g_pf;
    #pragma unroll 4
    for (int rr = 0; rr < 16; rr++) {
        int r = rg*16 + rr;
        float4 p = pf4[(size_t)sgp[r]*16 + cg];
        float dx = sdx[r], dy = sdy[r], dz = sdz[r];
        float pv[4] = {p.x, p.y, p.z, p.w};
        #pragma unroll
        for (int k = 0; k < 4; k++) {
            float y = pv[k] + fmaf(dx, wx[k], fmaf(dy, wy[k], fmaf(dz, wz[k], bb[k])));
            s[k] += y; s2[k] = fmaf(y, y, s2[k]);
        }
    }
    #pragma unroll
    for (int k = 0; k < 4; k++) { ps[c0+k][rg] = s[k]; pq[c0+k][rg] = s2[k]; }
    __syncthreads();
    if (t < 64) {
        double S = 0.0, Q = 0.0;
        #pragma unroll
        for (int g = 0; g < 16; g++) { S += (double)ps[t][g]; Q += (double)pq[t][g]; }
        g_part[(size_t)t*8192 + blk]       = S;
        g_part[(size_t)(128+t)*8192 + blk] = Q;
    }
}

// ---------------- BN finalize ----------------
__global__ void __launch_bounds__(256) k_fin(const float* __restrict__ ga,
                                             const float* __restrict__ be,
                                             int off, int nblk) {
    const int ch = blockIdx.x;
    const int t = threadIdx.x;
    double s = 0.0, s2 = 0.0;
    const double* p0 = g_part + (size_t)ch*8192;
    const double* p1 = g_part + (size_t)(128+ch)*8192;
    for (int i = t; i < nblk; i += 256) { s += p0[i]; s2 += p1[i]; }
    __shared__ double sh[256], sh2[256];
    sh[t] = s; sh2[t] = s2; __syncthreads();
    for (int o = 128; o; o >>= 1) {
        if (t < o) { sh[t] += sh[t+o]; sh2[t] += sh2[t+o]; }
        __syncthreads();
    }
    if (t == 0) {
        double mu  = sh[0]  / (double)NEq;
        double var = sh2[0] / (double)NEq - mu*mu;
        if (var < 0.0) var = 0.0;
        double sc = (double)ga[ch] / sqrt(var + 1e-5);
        g_scale[off+ch] = (float)sc;
        g_shift[off+ch] = (float)((double)be[ch] - mu*sc);
    }
}

// ---------------- layer1 (FFMA2 + lazy epilogue, R7) ----------------
__global__ void __launch_bounds__(128) k_layer1(const float* __restrict__ xyz,
                                                const float* __restrict__ W0,
                                                const float* __restrict__ b0,
                                                const float* __restrict__ W1,
                                                const float* __restrict__ b1) {
    extern __shared__ float sm[];
    float* xs  = sm;                   // [64][XS_PAD]
    float* Wt  = sm + 64*XS_PAD;       // [64][64]
    float* swx = Wt + 4096;
    float* swy = swx + 64; float* swz = swy + 64; float* sb = swz + 64;
    float* ssc = sb + 64;  float* ssh = ssc + 64;
    const int t = threadIdx.x;
    const int blk = blockIdx.x;
    for (int i = t; i < 4096; i += 128) Wt[i] = W1[(i & 63)*64 + (i >> 6)];
    if (t < 64) {
        swx[t] = W0[t*67+0]; swy[t] = W0[t*67+1]; swz[t] = W0[t*67+2];
        sb[t] = b0[t]; ssc[t] = g_scale[t]; ssh[t] = g_shift[t];
    }
    int R = blk*128 + t;
    int q = R >> 5, b = q >> 10;
    int gp = b*Nq + g_grp[R];
    float dx = __fsub_rn(xyz[gp*3+0], g_newxyz[3*q+0]);
    float dy = __fsub_rn(xyz[gp*3+1], g_newxyz[3*q+1]);
    float dz = __fsub_rn(xyz[gp*3+2], g_newxyz[3*q+2]);
    __syncthreads();
    const float4* pfv4 = (const float4*)g_pf;
    #pragma unroll
    for (int c4 = 0; c4 < 16; c4++) {
        float4 p = pfv4[(size_t)gp*16 + c4];
        float pv[4] = {p.x, p.y, p.z, p.w};
        #pragma unroll
        for (int k2 = 0; k2 < 4; k2++) {
            int c = c4*4 + k2;
            float y = pv[k2] + fmaf(dx, swx[c], fmaf(dy, swy[c], fmaf(dz, swz[c], sb[c])));
            xs[c*XS_PAD + t] = fmaxf(fmaf(ssc[c], y, ssh[c]), 0.0f);
        }
    }
    __syncthreads();
    const int r0 = (t & 15)*8, o0 = (t >> 4)*8;
    unsigned long long acc2[8][4];
    {
        ulonglong2 bA = *(const ulonglong2*)&b1[o0];
        ulonglong2 bB = *(const ulonglong2*)&b1[o0+4];
        unsigned long long bp[4] = {bA.x, bA.y, bB.x, bB.y};
        #pragma unroll
        for (int i = 0; i < 8; i++)
            #pragma unroll
            for (int j = 0; j < 4; j++) acc2[i][j] = bp[j];
    }
    for (int c = 0; c < 64; c++) {
        float4 xa = *(const float4*)&xs[c*XS_PAD + r0];
        float4 xc = *(const float4*)&xs[c*XS_PAD + r0 + 4];
        ulonglong2 wA = *(const ulonglong2*)&Wt[c*64 + o0];
        ulonglong2 wB = *(const ulonglong2*)&Wt[c*64 + o0 + 4];
        unsigned long long wp[4] = {wA.x, wA.y, wB.x, wB.y};
        float xr[8] = {xa.x,xa.y,xa.z,xa.w,xc.x,xc.y,xc.z,xc.w};
        unsigned long long xp[8];
        #pragma unroll
        for (int i = 0; i < 8; i++) PACK2(xp[i], xr[i], xr[i]);
        #pragma unroll
        for (int i = 0; i < 8; i++)
            #pragma unroll
            for (int j = 0; j < 4; j++) FMA2(acc2[i][j], xp[i], wp[j]);
    }
    #pragma unroll
    for (int i = 0; i < 8; i++) {
        size_t base = ((size_t)(blk*128 + r0 + i))*64 + o0;
        *(ulonglong2*)&g_y1[base]   = make_ulonglong2(acc2[i][0], acc2[i][1]);
        *(ulonglong2*)&g_y1[base+4] = make_ulonglong2(acc2[i][2], acc2[i][3]);
    }
    #pragma unroll
    for (int jp = 0; jp < 4; jp++) {
        float s0 = 0.0f, q0s = 0.0f, s1 = 0.0f, q1s = 0.0f;
        #pragma unroll
        for (int i = 0; i < 8; i++) {
            float a0, a1; UNPACK2(a0, a1, acc2[i][jp]);
            s0 += a0; q0s = fmaf(a0, a0, q0s);
            s1 += a1; q1s = fmaf(a1, a1, q1s);
        }
        #pragma unroll
        for (int off = 8; off; off >>= 1) {
            s0  += __shfl_down_sync(0xffffffffu, s0,  off, 16);
            q0s += __shfl_down_sync(0xffffffffu, q0s, off, 16);
            s1  += __shfl_down_sync(0xffffffffu, s1,  off, 16);
            q1s += __shfl_down_sync(0xffffffffu, q1s, off, 16);
        }
        if ((t & 15) == 0) {
            g_part[(size_t)(o0+2*jp)*8192 + blk]       = (double)s0;
            g_part[(size_t)(128+o0+2*jp)*8192 + blk]   = (double)q0s;
            g_part[(size_t)(o0+2*jp+1)*8192 + blk]     = (double)s1;
            g_part[(size_t)(128+o0+2*jp+1)*8192 + blk] = (double)q1s;
        }
    }
}

// ---------------- layer2 (FFMA2 + lazy epilogue, R7) ----------------
__global__ void __launch_bounds__(256, 2) k_layer2(const float* __restrict__ W2,
                                                   const float* __restrict__ b2) {
    extern __shared__ float sm[];
    float* xs  = sm;                   // [64][XS_PAD]
    float* Wt  = sm + 64*XS_PAD;       // [64][128]
    float* ssc = Wt + 8192;
    float* ssh = ssc + 64;
    const int t = threadIdx.x;
    const int blk = blockIdx.x;
    for (int i = t; i < 8192; i += 256) Wt[i] = W2[(i & 127)*64 + (i >> 7)];
    if (t < 64) { ssc[t] = g_scale[128+t]; ssh[t] = g_shift[128+t]; }
    __syncthreads();
    const float4* y1v = (const float4*)g_y1;
    #pragma unroll
    for (int jj = 0; jj < 8; jj++) {
        int idx = t + jj*256;
        int r = idx >> 4, c4 = idx & 15;
        float4 v = y1v[(size_t)(blk*128 + r)*16 + c4];
        float pv[4] = {v.x, v.y, v.z, v.w};
        #pragma unroll
        for (int k2 = 0; k2 < 4; k2++) {
            int c = c4*4 + k2;
            xs[c*XS_PAD + r] = fmaxf(fmaf(ssc[c], pv[k2], ssh[c]), 0.0f);
        }
    }
    __syncthreads();
    const int r0 = (t & 15)*8, o0 = (t >> 4)*8;
    unsigned long long acc2[8][4];
    {
        ulonglong2 bA = *(const ulonglong2*)&b2[o0];
        ulonglong2 bB = *(const ulonglong2*)&b2[o0+4];
        unsigned long long bp[4] = {bA.x, bA.y, bB.x, bB.y};
        #pragma unroll
        for (int i = 0; i < 8; i++)
            #pragma unroll
            for (int j = 0; j < 4; j++) acc2[i][j] = bp[j];
    }
    for (int c = 0; c < 64; c++) {
        float4 xa = *(const float4*)&xs[c*XS_PAD + r0];
        float4 xc = *(const float4*)&xs[c*XS_PAD + r0 + 4];
        ulonglong2 wA = *(const ulonglong2*)&Wt[c*128 + o0];
        ulonglong2 wB = *(const ulonglong2*)&Wt[c*128 + o0 + 4];
        unsigned long long wp[4] = {wA.x, wA.y, wB.x, wB.y};
        float xr[8] = {xa.x,xa.y,xa.z,xa.w,xc.x,xc.y,xc.z,xc.w};
        unsigned long long xp[8];
        #pragma unroll
        for (int i = 0; i < 8; i++) PACK2(xp[i], xr[i], xr[i]);
        #pragma unroll
        for (int i = 0; i < 8; i++)
            #pragma unroll
            for (int j = 0; j < 4; j++) FMA2(acc2[i][j], xp[i], wp[j]);
    }
    #pragma unroll
    for (int jp = 0; jp < 4; jp++) {
        float a0, a1; UNPACK2(a0, a1, acc2[0][jp]);
        float s0 = a0, q0s = a0*a0, mx0 = a0, mn0 = a0;
        float s1 = a1, q1s = a1*a1, mx1 = a1, mn1 = a1;
        #pragma unroll
        for (int i = 1; i < 8; i++) {
            UNPACK2(a0, a1, acc2[i][jp]);
            s0 += a0; q0s = fmaf(a0, a0, q0s); mx0 = fmaxf(mx0, a0); mn0 = fminf(mn0, a0);
            s1 += a1; q1s = fmaf(a1, a1, q1s); mx1 = fmaxf(mx1, a1); mn1 = fminf(mn1, a1);
        }
        #pragma unroll
        for (int off = 8; off; off >>= 1) {
            s0  += __shfl_down_sync(0xffffffffu, s0,  off, 16);
            q0s += __shfl_down_sync(0xffffffffu, q0s, off, 16);
            s1  += __shfl_down_sync(0xffffffffu, s1,  off, 16);
            q1s += __shfl_down_sync(0xffffffffu, q1s, off, 16);
        }
        if ((t & 15) == 0) {
            g_part[(size_t)(o0+2*jp)*8192 + blk]       = (double)s0;
            g_part[(size_t)(128+o0+2*jp)*8192 + blk]   = (double)q0s;
            g_part[(size_t)(o0+2*jp+1)*8192 + blk]     = (double)s1;
            g_part[(size_t)(128+o0+2*jp+1)*8192 + blk] = (double)q1s;
        }
        #pragma unroll
        for (int off = 2; off; off >>= 1) {
            mx0 = fmaxf(mx0, __shfl_down_sync(0xffffffffu, mx0, off, 4));
            mn0 = fminf(mn0, __shfl_down_sync(0xffffffffu, mn0, off, 4));
            mx1 = fmaxf(mx1, __shfl_down_sync(0xffffffffu, mx1, off, 4));
            mn1 = fminf(mn1, __shfl_down_sync(0xffffffffu, mn1, off, 4));
        }
        if ((t & 3) == 0) {
            int qg = blk*4 + ((t & 15) >> 2);
            g_maxv[(size_t)qg*128 + o0 + 2*jp]     = mx0;
            g_minv[(size_t)qg*128 + o0 + 2*jp]     = mn0;
            g_maxv[(size_t)qg*128 + o0 + 2*jp + 1] = mx1;
            g_minv[(size_t)qg*128 + o0 + 2*jp + 1] = mn1;
        }
    }
}

// ---------------- final: BN2+ReLU fused max-pool from min/max ----------------
__global__ void __launch_bounds__(256) k_maxpool(float* __restrict__ out) {
    int i = blockIdx.x*256 + threadIdx.x;
    int o = i & 127;
    float sc = g_scale[256+o], sh = g_shift[256+o];
    float v = (sc >= 0.0f) ? g_maxv[i] : g_minv[i];
    out[OUT_PTS + i] = fmaxf(fmaf(sc, v, sh), 0.0f);
}

// ---------------- launch (sequential; k_prep eliminated) ----------------
extern "C" void kernel_launch(void* const* d_in, const int* in_sizes, int n_in,
                              void* d_out, int out_size) {
    (void)in_sizes; (void)n_in; (void)out_size;
    const float* xyz    = (const float*)d_in[0];
    const float* points = (const float*)d_in[1];
    const float* W0  = (const float*)d_in[2];
    const float* b0  = (const float*)d_in[3];
    const float* g0  = (const float*)d_in[4];
    const float* bt0 = (const float*)d_in[5];
    const float* W1  = (const float*)d_in[6];
    const float* b1  = (const float*)d_in[7];
    const float* g1  = (const float*)d_in[8];
    const float* bt1 = (const float*)d_in[9];
    const float* W2  = (const float*)d_in[10];
    const float* b2  = (const float*)d_in[11];
    const float* g2  = (const float*)d_in[12];
    const float* bt2 = (const float*)d_in[13];
    float* out = (float*)d_out;

    const int SM_PF = (64*XS_PAD + 64*64) * 4;
    const int SM_L1 = (64*XS_PAD + 64*64 + 6*64) * 4;
    const int SM_L2 = (64*XS_PAD + 64*128 + 2*64) * 4;
    cudaFuncSetAttribute(k_pf,     cudaFuncAttributeMaxDynamicSharedMemorySize, SM_PF);
    cudaFuncSetAttribute(k_layer1, cudaFuncAttributeMaxDynamicSharedMemorySize, SM_L1);
    cudaFuncSetAttribute(k_layer2, cudaFuncAttributeMaxDynamicSharedMemorySize, SM_L2);

    k_pf<<<NP/128, 128, SM_PF>>>(points, W0);
    k_fps<<<Bq, 512>>>(xyz, out);
    k_ball<<<NQ/QPB, BT>>>(xyz);

    k_l0stats<<<NEq/256, 256>>>(xyz, W0, b0);
    k_fin<<<64, 256>>>(g0, bt0, 0, NEq/256);
    k_layer1<<<NEq/128, 128, SM_L1>>>(xyz, W0, b0, W1, b1);
    k_fin<<<64, 256>>>(g1, bt1, 128, NEq/128);
    k_layer2<<<NEq/128, 256, SM_L2>>>(W2, b2);
    k_fin<<<128, 256>>>(g2, bt2, 256, NEq/128);
    k_maxpool<<<NQ*128/256, 256>>>(out);
}

// round 14
// speedup vs baseline: 1.1772x; 1.1527x over previous
#include <cuda_runtime.h>
#include <cstdint>

#define Bq 16
#define Nq 4096
#define Sq 1024
#define Kq 32
#define NQ (Bq*Sq)          // 16384 queries
#define NP (Bq*Nq)          // 65536 points
#define NEq (NQ*Kq)         // 524288 rows
#define OUT_PTS (NQ*3)
#define XS_PAD 132
#define QPB 4               // queries per ball block
#define CAP 768             // candidate cap per query (mean 137, sd ~12)
#define BT 256              // ball block threads

// packed fp32x2 helpers (exact IEEE fp32 per lane; only add/mul/fma exist packed)
#define FMA2(d,a,b)   asm("fma.rn.f32x2 %0, %1, %2, %0;" : "+l"(d) : "l"(a), "l"(b))
#define ADD2(d,a,b)   asm("add.rn.f32x2 %0, %1, %2;" : "=l"(d) : "l"(a), "l"(b))
#define MUL2(d,a,b)   asm("mul.rn.f32x2 %0, %1, %2;" : "=l"(d) : "l"(a), "l"(b))
#define PACK2(d,x,y)  asm("mov.b64 %0, {%1, %2};" : "=l"(d) : "f"(x), "f"(y))
#define UNPACK2(x,y,d) asm("mov.b64 {%0, %1}, %2;" : "=f"(x), "=f"(y) : "l"(d))

// ---------------- scratch ----------------
__device__ float  g_newxyz[NQ*3];
__device__ int    g_grp[NEq];
__device__ float  g_pf[(size_t)NP*64];        // point features (layer0 w/o geom), 16MB
__device__ float  g_y1[(size_t)NEq*64];       // layer1 pre-BN output, 134MB
__device__ float  g_maxv[(size_t)NQ*128];
__device__ float  g_minv[(size_t)NQ*128];
__device__ double g_part[(size_t)256*8192];
__device__ float  g_scale[384];
__device__ float  g_shift[384];

// ---------------- FPS: smem xyz cache, packed body, REDUX two-level tail ----------------
__global__ void __launch_bounds__(512) k_fps(const float* __restrict__ xyz,
                                             float* __restrict__ out) {
    const int b = blockIdx.x;
    const int t = threadIdx.x;
    const int lane = t & 31, wid = t >> 5;
    const float* xb = xyz + b*Nq*3;
    __shared__ float sxy[Nq*3];                 // 48KB: whole batch resident in smem
    __shared__ unsigned swv[2][16];             // double-buffered warp value partials
    __shared__ int      swi[2][16];             // warp index partials
    {
        const float4* src = (const float4*)xb;
        float4* dst = (float4*)sxy;
        #pragma unroll
        for (int i = 0; i < (Nq*3/4)/512; i++) dst[t + i*512] = src[t + i*512];
    }
    __syncthreads();
    // pair j: points p0 = t + 2j*512 (lane0) and p1 = p0 + 512 (lane1); p0 < p1
    unsigned long long px2[4], py2[4], pz2[4];
    float dd[8];
    #pragma unroll
    for (int j = 0; j < 4; j++) {
        int p0 = t + (2*j)*512, p1 = p0 + 512;
        PACK2(px2[j], sxy[3*p0],   sxy[3*p1]);
        PACK2(py2[j], sxy[3*p0+1], sxy[3*p1+1]);
        PACK2(pz2[j], sxy[3*p0+2], sxy[3*p1+2]);
        dd[2*j] = 1e10f; dd[2*j+1] = 1e10f;
    }
    int far = 0;
    for (int i = 0; i < Sq; i++) {
        float cx = sxy[3*far], cy = sxy[3*far+1], cz = sxy[3*far+2];
        if (t == 0) {
            int o = (b*Sq + i)*3;
            g_newxyz[o] = cx; g_newxyz[o+1] = cy; g_newxyz[o+2] = cz;
            out[o] = cx; out[o+1] = cy; out[o+2] = cz;
        }
        float ncx = -cx, ncy = -cy, ncz = -cz;   // x - c == x + (-c) exactly
        unsigned long long ncx2, ncy2, ncz2;
        PACK2(ncx2, ncx, ncx); PACK2(ncy2, ncy, ncy); PACK2(ncz2, ncz, ncz);
        float bv = -1.0f; int bi = 0;
        #pragma unroll
        for (int j = 0; j < 4; j++) {
            unsigned long long dx, dy, dz, sx, sy, sz, sA, sB;
            ADD2(dx, px2[j], ncx2);
            ADD2(dy, py2[j], ncy2);
            ADD2(dz, pz2[j], ncz2);
            MUL2(sx, dx, dx);
            MUL2(sy, dy, dy);
            MUL2(sz, dz, dz);
            ADD2(sA, sx, sy);        // (dx^2 + dy^2)
            ADD2(sB, sA, sz);        // + dz^2 — exact reference fold per lane
            float d0, d1; UNPACK2(d0, d1, sB);
            float nd0 = fminf(dd[2*j], d0);   dd[2*j]   = nd0;
            if (nd0 > bv) { bv = nd0; bi = t + (2*j)*512; }     // strict > keeps lowest idx
            float nd1 = fminf(dd[2*j+1], d1); dd[2*j+1] = nd1;
            if (nd1 > bv) { bv = nd1; bi = t + (2*j+1)*512; }
        }
        // intra-warp: REDUX max on value bits (dd>=0 -> order-preserving), REDUX min on idx
        unsigned vb = __float_as_uint(bv);                 // bv >= 0 after the loop
        unsigned vmax = __reduce_max_sync(0xffffffffu, vb);
        int cand = (vb == vmax) ? bi : 0x7fffffff;
        int bimin = __reduce_min_sync(0xffffffffu, cand);
        const int par = i & 1;
        if (lane == 0) { swv[par][wid] = vmax; swi[par][wid] = bimin; }
        __syncthreads();
        // cross-warp: every warp redundantly reduces all 16 partials via 2 REDUX
        unsigned v2 = swv[par][lane & 15];
        int i2 = swi[par][lane & 15];
        unsigned gmax = __reduce_max_sync(0xffffffffu, v2);
        int c2 = (v2 == gmax) ? i2 : 0x7fffffff;
        far = __reduce_min_sync(0xffffffffu, c2);
        // no second barrier: next iteration uses the other buffer
    }
}

// ---------------- ball query: vectorized sweep (3xLDG.128 per 4 pts), inline |p|^2 ----------------
__global__ void __launch_bounds__(BT) k_ball(const float* __restrict__ xyz) {
    const int blk = blockIdx.x;
    const int q0 = blk * QPB;
    const int b = q0 >> 10;
    const int t = threadIdx.x;
    __shared__ unsigned long long ck[QPB][CAP];
    __shared__ int scnt[QPB];
    __shared__ int sm_m[QPB];
    __shared__ int soff[QPB+1];
    __shared__ int ssel[QPB][Kq];
    if (t < QPB) scnt[t] = 0;
    __syncthreads();
    float cx[QPB], cy[QPB], cz[QPB], sa[QPB];
    #pragma unroll
    for (int j = 0; j < QPB; j++) {
        cx[j] = g_newxyz[3*(q0+j)]; cy[j] = g_newxyz[3*(q0+j)+1]; cz[j] = g_newxyz[3*(q0+j)+2];
        sa[j] = __fadd_rn(__fadd_rn(__fmul_rn(cx[j],cx[j]), __fmul_rn(cy[j],cy[j])), __fmul_rn(cz[j],cz[j]));
    }
    const float4* xb4 = (const float4*)(xyz + (size_t)b*Nq*3);   // batch base is 16B-aligned
    #pragma unroll
    for (int k = 0; k < Nq/(4*BT); k++) {
        int m = t + k*BT;                       // 4-point group
        float4 f0 = xb4[3*m], f1 = xb4[3*m+1], f2 = xb4[3*m+2];
        float gx[4] = {f0.x, f0.w, f1.z, f2.y};
        float gy[4] = {f0.y, f1.x, f1.w, f2.z};
        float gz[4] = {f0.z, f1.y, f2.x, f2.w};
        #pragma unroll
        for (int u = 0; u < 4; u++) {
            int n = 4*m + u;
            float x = gx[u], y = gy[u], z = gz[u];
            float sn = __fadd_rn(__fadd_rn(__fmul_rn(x,x), __fmul_rn(y,y)), __fmul_rn(z,z));
            #pragma unroll
            for (int j = 0; j < QPB; j++) {
                float dot = __fadd_rn(__fadd_rn(__fmul_rn(x,cx[j]), __fmul_rn(y,cy[j])), __fmul_rn(z,cz[j]));
                float d = __fsub_rn(__fadd_rn(sa[j], sn), __fmul_rn(2.0f, dot));
                if (d <= 0.04f) {
                    unsigned ub = __float_as_uint(d);
                    ub = ((int)ub < 0) ? ~ub : (ub | 0x80000000u);   // monotone float->uint
                    int p = atomicAdd(&scnt[j], 1);
                    if (p < CAP) ck[j][p] = ((unsigned long long)ub << 32) | (unsigned)n;
                }
            }
        }
    }
    __syncthreads();
    if (t == 0) {
        int acc = 0;
        #pragma unroll
        for (int j = 0; j < QPB; j++) {
            soff[j] = acc;
            int c = scnt[j] < CAP ? scnt[j] : CAP;
            sm_m[j] = c < Kq ? c : Kq;
            acc += c;
        }
        soff[QPB] = acc;
    }
    __syncthreads();
    // flattened (query, candidate) ranking
    const int total = soff[QPB];
    for (int w = t; w < total; w += BT) {
        int j = 0;
        #pragma unroll
        for (int jj = 1; jj < QPB; jj++) j += (w >= soff[jj]);
        int p = w - soff[j];
        int cnt = soff[j+1] - soff[j];
        unsigned long long mk = ck[j][p];
        int r = 0;
        for (int i = 0; i < cnt; i++) r += (ck[j][i] < mk);
        if (r < Kq) ssel[j][r] = (int)(unsigned)mk;
    }
    __syncthreads();
    if (t < QPB*Kq) {
        int j = t >> 5, k = t & 31;
        g_grp[(q0+j)*Kq + k] = ssel[j][k < sm_m[j] ? k : 0];
    }
}

// ---------------- point-feature GEMM (FFMA2 mainloop, R7) ----------------
__global__ void __launch_bounds__(128) k_pf(const float* __restrict__ points,
                                            const float* __restrict__ W0) {
    extern __shared__ float sm[];
    float* xs = sm;                   // [64][XS_PAD]
    float* Wt = sm + 64*XS_PAD;       // [64][64]
    const int t = threadIdx.x;
    const int blk = blockIdx.x;
    for (int i = t; i < 4096; i += 128) Wt[i] = W0[(i & 63)*67 + 3 + (i >> 6)];
    const float4* pts4 = (const float4*)points;
    #pragma unroll
    for (int jj = 0; jj < 16; jj++) {
        int idx = t + jj*128;
        int r = idx >> 4, c4 = idx & 15;
        float4 v = pts4[(size_t)(blk*128 + r)*16 + c4];
        xs[(4*c4+0)*XS_PAD + r] = v.x;
        xs[(4*c4+1)*XS_PAD + r] = v.y;
        xs[(4*c4+2)*XS_PAD + r] = v.z;
        xs[(4*c4+3)*XS_PAD + r] = v.w;
    }
    __syncthreads();
    const int r0 = (t & 15)*8, o0 = (t >> 4)*8;
    unsigned long long acc2[8][4];
    #pragma unroll
    for (int i = 0; i < 8; i++)
        #pragma unroll
        for (int j = 0; j < 4; j++) acc2[i][j] = 0ull;
    for (int c = 0; c < 64; c++) {
        float4 xa = *(const float4*)&xs[c*XS_PAD + r0];
        float4 xc = *(const float4*)&xs[c*XS_PAD + r0 + 4];
        ulonglong2 wA = *(const ulonglong2*)&Wt[c*64 + o0];
        ulonglong2 wB = *(const ulonglong2*)&Wt[c*64 + o0 + 4];
        unsigned long long wp[4] = {wA.x, wA.y, wB.x, wB.y};
        float xr[8] = {xa.x,xa.y,xa.z,xa.w,xc.x,xc.y,xc.z,xc.w};
        unsigned long long xp[8];
        #pragma unroll
        for (int i = 0; i < 8; i++) PACK2(xp[i], xr[i], xr[i]);
        #pragma unroll
        for (int i = 0; i < 8; i++)
            #pragma unroll
            for (int j = 0; j < 4; j++) FMA2(acc2[i][j], xp[i], wp[j]);
    }
    #pragma unroll
    for (int i = 0; i < 8; i++) {
        size_t base = ((size_t)(blk*128 + r0 + i))*64 + o0;
        *(ulonglong2*)&g_pf[base]   = make_ulonglong2(acc2[i][0], acc2[i][1]);
        *(ulonglong2*)&g_pf[base+4] = make_ulonglong2(acc2[i][2], acc2[i][3]);
    }
}

// ---------------- layer0 stats: vectorized gather (LDG.128, warp-coalesced rows) ----------------
__global__ void __launch_bounds__(256) k_l0stats(const float* __restrict__ xyz,
                                                 const float* __restrict__ W0,
                                                 const float* __restrict__ b0) {
    __shared__ int   sgp[256];
    __shared__ float sdx[256], sdy[256], sdz[256];
    __shared__ float swx[64], swy[64], swz[64], sb[64];
    __shared__ float ps[64][17], pq[64][17];
    const int t = threadIdx.x;
    const int blk = blockIdx.x;
    if (t < 64) {
        swx[t] = W0[t*67+0]; swy[t] = W0[t*67+1]; swz[t] = W0[t*67+2]; sb[t] = b0[t];
    }
    {
        int R = blk*256 + t;
        int q = R >> 5, b = q >> 10;
        int gp = b*Nq + g_grp[R];
        sgp[t] = gp;
        sdx[t] = __fsub_rn(xyz[gp*3+0], g_newxyz[3*q+0]);
        sdy[t] = __fsub_rn(xyz[gp*3+1], g_newxyz[3*q+1]);
        sdz[t] = __fsub_rn(xyz[gp*3+2], g_newxyz[3*q+2]);
    }
    __syncthreads();
    const int cg = t & 15, rg = t >> 4;
    const int c0 = cg*4;
    float wx[4], wy[4], wz[4], bb[4];
    #pragma unroll
    for (int k = 0; k < 4; k++) { wx[k]=swx[c0+k]; wy[k]=swy[c0+k]; wz[k]=swz[c0+k]; bb[k]=sb[c0+k]; }
    float s[4] = {0,0,0,0}, s2[4] = {0,0,0,0};
    const float4* pf4 = (const float4*)g_pf;
    #pragma unroll 4
    for (int rr = 0; rr < 16; rr++) {
        int r = rg*16 + rr;
        float4 p = pf4[(size_t)sgp[r]*16 + cg];
        float dx = sdx[r], dy = sdy[r], dz = sdz[r];
        float pv[4] = {p.x, p.y, p.z, p.w};
        #pragma unroll
        for (int k = 0; k < 4; k++) {
            float y = pv[k] + fmaf(dx, wx[k], fmaf(dy, wy[k], fmaf(dz, wz[k], bb[k])));
            s[k] += y; s2[k] = fmaf(y, y, s2[k]);
        }
    }
    #pragma unroll
    for (int k = 0; k < 4; k++) { ps[c0+k][rg] = s[k]; pq[c0+k][rg] = s2[k]; }
    __syncthreads();
    if (t < 64) {
        double S = 0.0, Q = 0.0;
        #pragma unroll
        for (int g = 0; g < 16; g++) { S += (double)ps[t][g]; Q += (double)pq[t][g]; }
        g_part[(size_t)t*8192 + blk]       = S;
        g_part[(size_t)(128+t)*8192 + blk] = Q;
    }
}

// ---------------- BN finalize ----------------
__global__ void __launch_bounds__(256) k_fin(const float* __restrict__ ga,
                                             const float* __restrict__ be,
                                             int off, int nblk) {
    const int ch = blockIdx.x;
    const int t = threadIdx.x;
    double s = 0.0, s2 = 0.0;
    const double* p0 = g_part + (size_t)ch*8192;
    const double* p1 = g_part + (size_t)(128+ch)*8192;
    for (int i = t; i < nblk; i += 256) { s += p0[i]; s2 += p1[i]; }
    __shared__ double sh[256], sh2[256];
    sh[t] = s; sh2[t] = s2; __syncthreads();
    for (int o = 128; o; o >>= 1) {
        if (t < o) { sh[t] += sh[t+o]; sh2[t] += sh2[t+o]; }
        __syncthreads();
    }
    if (t == 0) {
        double mu  = sh[0]  / (double)NEq;
        double var = sh2[0] / (double)NEq - mu*mu;
        if (var < 0.0) var = 0.0;
        double sc = (double)ga[ch] / sqrt(var + 1e-5);
        g_scale[off+ch] = (float)sc;
        g_shift[off+ch] = (float)((double)be[ch] - mu*sc);
    }
}

// ---------------- layer1 (FFMA2 + lazy epilogue, R7) ----------------
__global__ void __launch_bounds__(128) k_layer1(const float* __restrict__ xyz,
                                                const float* __restrict__ W0,
                                                const float* __restrict__ b0,
                                                const float* __restrict__ W1,
                                                const float* __restrict__ b1) {
    extern __shared__ float sm[];
    float* xs  = sm;                   // [64][XS_PAD]
    float* Wt  = sm + 64*XS_PAD;       // [64][64]
    float* swx = Wt + 4096;
    float* swy = swx + 64; float* swz = swy + 64; float* sb = swz + 64;
    float* ssc = sb + 64;  float* ssh = ssc + 64;
    const int t = threadIdx.x;
    const int blk = blockIdx.x;
    for (int i = t; i < 4096; i += 128) Wt[i] = W1[(i & 63)*64 + (i >> 6)];
    if (t < 64) {
        swx[t] = W0[t*67+0]; swy[t] = W0[t*67+1]; swz[t] = W0[t*67+2];
        sb[t] = b0[t]; ssc[t] = g_scale[t]; ssh[t] = g_shift[t];
    }
    int R = blk*128 + t;
    int q = R >> 5, b = q >> 10;
    int gp = b*Nq + g_grp[R];
    float dx = __fsub_rn(xyz[gp*3+0], g_newxyz[3*q+0]);
    float dy = __fsub_rn(xyz[gp*3+1], g_newxyz[3*q+1]);
    float dz = __fsub_rn(xyz[gp*3+2], g_newxyz[3*q+2]);
    __syncthreads();
    const float4* pfv4 = (const float4*)g_pf;
    #pragma unroll
    for (int c4 = 0; c4 < 16; c4++) {
        float4 p = pfv4[(size_t)gp*16 + c4];
        float pv[4] = {p.x, p.y, p.z, p.w};
        #pragma unroll
        for (int k2 = 0; k2 < 4; k2++) {
            int c = c4*4 + k2;
            float y = pv[k2] + fmaf(dx, swx[c], fmaf(dy, swy[c], fmaf(dz, swz[c], sb[c])));
            xs[c*XS_PAD + t] = fmaxf(fmaf(ssc[c], y, ssh[c]), 0.0f);
        }
    }
    __syncthreads();
    const int r0 = (t & 15)*8, o0 = (t >> 4)*8;
    unsigned long long acc2[8][4];
    {
        ulonglong2 bA = *(const ulonglong2*)&b1[o0];
        ulonglong2 bB = *(const ulonglong2*)&b1[o0+4];
        unsigned long long bp[4] = {bA.x, bA.y, bB.x, bB.y};
        #pragma unroll
        for (int i = 0; i < 8; i++)
            #pragma unroll
            for (int j = 0; j < 4; j++) acc2[i][j] = bp[j];
    }
    for (int c = 0; c < 64; c++) {
        float4 xa = *(const float4*)&xs[c*XS_PAD + r0];
        float4 xc = *(const float4*)&xs[c*XS_PAD + r0 + 4];
        ulonglong2 wA = *(const ulonglong2*)&Wt[c*64 + o0];
        ulonglong2 wB = *(const ulonglong2*)&Wt[c*64 + o0 + 4];
        unsigned long long wp[4] = {wA.x, wA.y, wB.x, wB.y};
        float xr[8] = {xa.x,xa.y,xa.z,xa.w,xc.x,xc.y,xc.z,xc.w};
        unsigned long long xp[8];
        #pragma unroll
        for (int i = 0; i < 8; i++) PACK2(xp[i], xr[i], xr[i]);
        #pragma unroll
        for (int i = 0; i < 8; i++)
            #pragma unroll
            for (int j = 0; j < 4; j++) FMA2(acc2[i][j], xp[i], wp[j]);
    }
    #pragma unroll
    for (int i = 0; i < 8; i++) {
        size_t base = ((size_t)(blk*128 + r0 + i))*64 + o0;
        *(ulonglong2*)&g_y1[base]   = make_ulonglong2(acc2[i][0], acc2[i][1]);
        *(ulonglong2*)&g_y1[base+4] = make_ulonglong2(acc2[i][2], acc2[i][3]);
    }
    #pragma unroll
    for (int jp = 0; jp < 4; jp++) {
        float s0 = 0.0f, q0s = 0.0f, s1 = 0.0f, q1s = 0.0f;
        #pragma unroll
        for (int i = 0; i < 8; i++) {
            float a0, a1; UNPACK2(a0, a1, acc2[i][jp]);
            s0 += a0; q0s = fmaf(a0, a0, q0s);
            s1 += a1; q1s = fmaf(a1, a1, q1s);
        }
        #pragma unroll
        for (int off = 8; off; off >>= 1) {
            s0  += __shfl_down_sync(0xffffffffu, s0,  off, 16);
            q0s += __shfl_down_sync(0xffffffffu, q0s, off, 16);
            s1  += __shfl_down_sync(0xffffffffu, s1,  off, 16);
            q1s += __shfl_down_sync(0xffffffffu, q1s, off, 16);
        }
        if ((t & 15) == 0) {
            g_part[(size_t)(o0+2*jp)*8192 + blk]       = (double)s0;
            g_part[(size_t)(128+o0+2*jp)*8192 + blk]   = (double)q0s;
            g_part[(size_t)(o0+2*jp+1)*8192 + blk]     = (double)s1;
            g_part[(size_t)(128+o0+2*jp+1)*8192 + blk] = (double)q1s;
        }
    }
}

// ---------------- layer2 (FFMA2 + lazy epilogue, R7) ----------------
__global__ void __launch_bounds__(256, 2) k_layer2(const float* __restrict__ W2,
                                                   const float* __restrict__ b2) {
    extern __shared__ float sm[];
    float* xs  = sm;                   // [64][XS_PAD]
    float* Wt  = sm + 64*XS_PAD;       // [64][128]
    float* ssc = Wt + 8192;
    float* ssh = ssc + 64;
    const int t = threadIdx.x;
    const int blk = blockIdx.x;
    for (int i = t; i < 8192; i += 256) Wt[i] = W2[(i & 127)*64 + (i >> 7)];
    if (t < 64) { ssc[t] = g_scale[128+t]; ssh[t] = g_shift[128+t]; }
    __syncthreads();
    const float4* y1v = (const float4*)g_y1;
    #pragma unroll
    for (int jj = 0; jj < 8; jj++) {
        int idx = t + jj*256;
        int r = idx >> 4, c4 = idx & 15;
        float4 v = y1v[(size_t)(blk*128 + r)*16 + c4];
        float pv[4] = {v.x, v.y, v.z, v.w};
        #pragma unroll
        for (int k2 = 0; k2 < 4; k2++) {
            int c = c4*4 + k2;
            xs[c*XS_PAD + r] = fmaxf(fmaf(ssc[c], pv[k2], ssh[c]), 0.0f);
        }
    }
    __syncthreads();
    const int r0 = (t & 15)*8, o0 = (t >> 4)*8;
    unsigned long long acc2[8][4];
    {
        ulonglong2 bA = *(const ulonglong2*)&b2[o0];
        ulonglong2 bB = *(const ulonglong2*)&b2[o0+4];
        unsigned long long bp[4] = {bA.x, bA.y, bB.x, bB.y};
        #pragma unroll
        for (int i = 0; i < 8; i++)
            #pragma unroll
            for (int j = 0; j < 4; j++) acc2[i][j] = bp[j];
    }
    for (int c = 0; c < 64; c++) {
        float4 xa = *(const float4*)&xs[c*XS_PAD + r0];
        float4 xc = *(const float4*)&xs[c*XS_PAD + r0 + 4];
        ulonglong2 wA = *(const ulonglong2*)&Wt[c*128 + o0];
        ulonglong2 wB = *(const ulonglong2*)&Wt[c*128 + o0 + 4];
        unsigned long long wp[4] = {wA.x, wA.y, wB.x, wB.y};
        float xr[8] = {xa.x,xa.y,xa.z,xa.w,xc.x,xc.y,xc.z,xc.w};
        unsigned long long xp[8];
        #pragma unroll
        for (int i = 0; i < 8; i++) PACK2(xp[i], xr[i], xr[i]);
        #pragma unroll
        for (int i = 0; i < 8; i++)
            #pragma unroll
            for (int j = 0; j < 4; j++) FMA2(acc2[i][j], xp[i], wp[j]);
    }
    #pragma unroll
    for (int jp = 0; jp < 4; jp++) {
        float a0, a1; UNPACK2(a0, a1, acc2[0][jp]);
        float s0 = a0, q0s = a0*a0, mx0 = a0, mn0 = a0;
        float s1 = a1, q1s = a1*a1, mx1 = a1, mn1 = a1;
        #pragma unroll
        for (int i = 1; i < 8; i++) {
            UNPACK2(a0, a1, acc2[i][jp]);
            s0 += a0; q0s = fmaf(a0, a0, q0s); mx0 = fmaxf(mx0, a0); mn0 = fminf(mn0, a0);
            s1 += a1; q1s = fmaf(a1, a1, q1s); mx1 = fmaxf(mx1, a1); mn1 = fminf(mn1, a1);
        }
        #pragma unroll
        for (int off = 8; off; off >>= 1) {
            s0  += __shfl_down_sync(0xffffffffu, s0,  off, 16);
            q0s += __shfl_down_sync(0xffffffffu, q0s, off, 16);
            s1  += __shfl_down_sync(0xffffffffu, s1,  off, 16);
            q1s += __shfl_down_sync(0xffffffffu, q1s, off, 16);
        }
        if ((t & 15) == 0) {
            g_part[(size_t)(o0+2*jp)*8192 + blk]       = (double)s0;
            g_part[(size_t)(128+o0+2*jp)*8192 + blk]   = (double)q0s;
            g_part[(size_t)(o0+2*jp+1)*8192 + blk]     = (double)s1;
            g_part[(size_t)(128+o0+2*jp+1)*8192 + blk] = (double)q1s;
        }
        #pragma unroll
        for (int off = 2; off; off >>= 1) {
            mx0 = fmaxf(mx0, __shfl_down_sync(0xffffffffu, mx0, off, 4));
            mn0 = fminf(mn0, __shfl_down_sync(0xffffffffu, mn0, off, 4));
            mx1 = fmaxf(mx1, __shfl_down_sync(0xffffffffu, mx1, off, 4));
            mn1 = fminf(mn1, __shfl_down_sync(0xffffffffu, mn1, off, 4));
        }
        if ((t & 3) == 0) {
            int qg = blk*4 + ((t & 15) >> 2);
            g_maxv[(size_t)qg*128 + o0 + 2*jp]     = mx0;
            g_minv[(size_t)qg*128 + o0 + 2*jp]     = mn0;
            g_maxv[(size_t)qg*128 + o0 + 2*jp + 1] = mx1;
            g_minv[(size_t)qg*128 + o0 + 2*jp + 1] = mn1;
        }
    }
}

// ---------------- final: BN2+ReLU fused max-pool from min/max ----------------
__global__ void __launch_bounds__(256) k_maxpool(float* __restrict__ out) {
    int i = blockIdx.x*256 + threadIdx.x;
    int o = i & 127;
    float sc = g_scale[256+o], sh = g_shift[256+o];
    float v = (sc >= 0.0f) ? g_maxv[i] : g_minv[i];
    out[OUT_PTS + i] = fmaxf(fmaf(sc, v, sh), 0.0f);
}

// ---------------- launch (sequential) ----------------
extern "C" void kernel_launch(void* const* d_in, const int* in_sizes, int n_in,
                              void* d_out, int out_size) {
    (void)in_sizes; (void)n_in; (void)out_size;
    const float* xyz    = (const float*)d_in[0];
    const float* points = (const float*)d_in[1];
    const float* W0  = (const float*)d_in[2];
    const float* b0  = (const float*)d_in[3];
    const float* g0  = (const float*)d_in[4];
    const float* bt0 = (const float*)d_in[5];
    const float* W1  = (const float*)d_in[6];
    const float* b1  = (const float*)d_in[7];
    const float* g1  = (const float*)d_in[8];
    const float* bt1 = (const float*)d_in[9];
    const float* W2  = (const float*)d_in[10];
    const float* b2  = (const float*)d_in[11];
    const float* g2  = (const float*)d_in[12];
    const float* bt2 = (const float*)d_in[13];
    float* out = (float*)d_out;

    const int SM_PF = (64*XS_PAD + 64*64) * 4;
    const int SM_L1 = (64*XS_PAD + 64*64 + 6*64) * 4;
    const int SM_L2 = (64*XS_PAD + 64*128 + 2*64) * 4;
    cudaFuncSetAttribute(k_pf,     cudaFuncAttributeMaxDynamicSharedMemorySize, SM_PF);
    cudaFuncSetAttribute(k_layer1, cudaFuncAttributeMaxDynamicSharedMemorySize, SM_L1);
    cudaFuncSetAttribute(k_layer2, cudaFuncAttributeMaxDynamicSharedMemorySize, SM_L2);

    k_pf<<<NP/128, 128, SM_PF>>>(points, W0);
    k_fps<<<Bq, 512>>>(xyz, out);
    k_ball<<<NQ/QPB, BT>>>(xyz);

    k_l0stats<<<NEq/256, 256>>>(xyz, W0, b0);
    k_fin<<<64, 256>>>(g0, bt0, 0, NEq/256);
    k_layer1<<<NEq/128, 128, SM_L1>>>(xyz, W0, b0, W1, b1);
    k_fin<<<64, 256>>>(g1, bt1, 128, NEq/128);
    k_layer2<<<NEq/128, 256, SM_L2>>>(W2, b2);
    k_fin<<<128, 256>>>(g2, bt2, 256, NEq/128);
    k_maxpool<<<NQ*128/256, 256>>>(out);
}

// round 15
// speedup vs baseline: 1.3698x; 1.1635x over previous
#include <cuda_runtime.h>
#include <cstdint>

#define Bq 16
#define Nq 4096
#define Sq 1024
#define Kq 32
#define NQ (Bq*Sq)          // 16384 queries
#define NP (Bq*Nq)          // 65536 points
#define NEq (NQ*Kq)         // 524288 rows
#define OUT_PTS (NQ*3)
#define XS_PAD 132
#define WP1 68              // padded Wt stride for COUT=64  (272B rows, 16B-aligned)
#define WP2 132             // padded Wt stride for COUT=128 (528B rows, 16B-aligned)
#define QPB 4               // queries per ball block
#define CAP 768             // candidate cap per query (mean 137, sd ~12)
#define BT 256              // ball block threads

// packed fp32x2 helpers (exact IEEE fp32 per lane; only add/mul/fma exist packed)
#define FMA2(d,a,b)   asm("fma.rn.f32x2 %0, %1, %2, %0;" : "+l"(d) : "l"(a), "l"(b))
#define ADD2(d,a,b)   asm("add.rn.f32x2 %0, %1, %2;" : "=l"(d) : "l"(a), "l"(b))
#define MUL2(d,a,b)   asm("mul.rn.f32x2 %0, %1, %2;" : "=l"(d) : "l"(a), "l"(b))
#define PACK2(d,x,y)  asm("mov.b64 %0, {%1, %2};" : "=l"(d) : "f"(x), "f"(y))
#define UNPACK2(x,y,d) asm("mov.b64 {%0, %1}, %2;" : "=f"(x), "=f"(y) : "l"(d))

// ---------------- scratch ----------------
__device__ float  g_newxyz[NQ*3];
__device__ int    g_grp[NEq];
__device__ float  g_pf[(size_t)NP*64];        // point features (layer0 w/o geom), 16MB
__device__ float  g_y1[(size_t)NEq*64];       // layer1 pre-BN output, 134MB
__device__ float  g_maxv[(size_t)NQ*128];
__device__ float  g_minv[(size_t)NQ*128];
__device__ double g_part[(size_t)256*8192];
__device__ float  g_scale[384];
__device__ float  g_shift[384];

// ---------------- FPS: smem xyz cache, packed body, REDUX two-level tail ----------------
__global__ void __launch_bounds__(512) k_fps(const float* __restrict__ xyz,
                                             float* __restrict__ out) {
    const int b = blockIdx.x;
    const int t = threadIdx.x;
    const int lane = t & 31, wid = t >> 5;
    const float* xb = xyz + b*Nq*3;
    __shared__ float sxy[Nq*3];                 // 48KB: whole batch resident in smem
    __shared__ unsigned swv[2][16];             // double-buffered warp value partials
    __shared__ int      swi[2][16];             // warp index partials
    {
        const float4* src = (const float4*)xb;
        float4* dst = (float4*)sxy;
        #pragma unroll
        for (int i = 0; i < (Nq*3/4)/512; i++) dst[t + i*512] = src[t + i*512];
    }
    __syncthreads();
    unsigned long long px2[4], py2[4], pz2[4];
    float dd[8];
    #pragma unroll
    for (int j = 0; j < 4; j++) {
        int p0 = t + (2*j)*512, p1 = p0 + 512;
        PACK2(px2[j], sxy[3*p0],   sxy[3*p1]);
        PACK2(py2[j], sxy[3*p0+1], sxy[3*p1+1]);
        PACK2(pz2[j], sxy[3*p0+2], sxy[3*p1+2]);
        dd[2*j] = 1e10f; dd[2*j+1] = 1e10f;
    }
    int far = 0;
    for (int i = 0; i < Sq; i++) {
        float cx = sxy[3*far], cy = sxy[3*far+1], cz = sxy[3*far+2];
        if (t == 0) {
            int o = (b*Sq + i)*3;
            g_newxyz[o] = cx; g_newxyz[o+1] = cy; g_newxyz[o+2] = cz;
            out[o] = cx; out[o+1] = cy; out[o+2] = cz;
        }
        float ncx = -cx, ncy = -cy, ncz = -cz;   // x - c == x + (-c) exactly
        unsigned long long ncx2, ncy2, ncz2;
        PACK2(ncx2, ncx, ncx); PACK2(ncy2, ncy, ncy); PACK2(ncz2, ncz, ncz);
        float bv = -1.0f; int bi = 0;
        #pragma unroll
        for (int j = 0; j < 4; j++) {
            unsigned long long dx, dy, dz, sx, sy, sz, sA, sB;
            ADD2(dx, px2[j], ncx2);
            ADD2(dy, py2[j], ncy2);
            ADD2(dz, pz2[j], ncz2);
            MUL2(sx, dx, dx);
            MUL2(sy, dy, dy);
            MUL2(sz, dz, dz);
            ADD2(sA, sx, sy);
            ADD2(sB, sA, sz);        // exact reference fold per lane
            float d0, d1; UNPACK2(d0, d1, sB);
            float nd0 = fminf(dd[2*j], d0);   dd[2*j]   = nd0;
            if (nd0 > bv) { bv = nd0; bi = t + (2*j)*512; }
            float nd1 = fminf(dd[2*j+1], d1); dd[2*j+1] = nd1;
            if (nd1 > bv) { bv = nd1; bi = t + (2*j+1)*512; }
        }
        unsigned vb = __float_as_uint(bv);
        unsigned vmax = __reduce_max_sync(0xffffffffu, vb);
        int cand = (vb == vmax) ? bi : 0x7fffffff;
        int bimin = __reduce_min_sync(0xffffffffu, cand);
        const int par = i & 1;
        if (lane == 0) { swv[par][wid] = vmax; swi[par][wid] = bimin; }
        __syncthreads();
        unsigned v2 = swv[par][lane & 15];
        int i2 = swi[par][lane & 15];
        unsigned gmax = __reduce_max_sync(0xffffffffu, v2);
        int c2 = (v2 == gmax) ? i2 : 0x7fffffff;
        far = __reduce_min_sync(0xffffffffu, c2);
    }
}

// ---------------- ball query: vectorized sweep, flattened rank ----------------
__global__ void __launch_bounds__(BT) k_ball(const float* __restrict__ xyz) {
    const int blk = blockIdx.x;
    const int q0 = blk * QPB;
    const int b = q0 >> 10;
    const int t = threadIdx.x;
    __shared__ unsigned long long ck[QPB][CAP];
    __shared__ int scnt[QPB];
    __shared__ int sm_m[QPB];
    __shared__ int soff[QPB+1];
    __shared__ int ssel[QPB][Kq];
    if (t < QPB) scnt[t] = 0;
    __syncthreads();
    float cx[QPB], cy[QPB], cz[QPB], sa[QPB];
    #pragma unroll
    for (int j = 0; j < QPB; j++) {
        cx[j] = g_newxyz[3*(q0+j)]; cy[j] = g_newxyz[3*(q0+j)+1]; cz[j] = g_newxyz[3*(q0+j)+2];
        sa[j] = __fadd_rn(__fadd_rn(__fmul_rn(cx[j],cx[j]), __fmul_rn(cy[j],cy[j])), __fmul_rn(cz[j],cz[j]));
    }
    const float4* xb4 = (const float4*)(xyz + (size_t)b*Nq*3);
    #pragma unroll
    for (int k = 0; k < Nq/(4*BT); k++) {
        int m = t + k*BT;
        float4 f0 = xb4[3*m], f1 = xb4[3*m+1], f2 = xb4[3*m+2];
        float gx[4] = {f0.x, f0.w, f1.z, f2.y};
        float gy[4] = {f0.y, f1.x, f1.w, f2.z};
        float gz[4] = {f0.z, f1.y, f2.x, f2.w};
        #pragma unroll
        for (int u = 0; u < 4; u++) {
            int n = 4*m + u;
            float x = gx[u], y = gy[u], z = gz[u];
            float sn = __fadd_rn(__fadd_rn(__fmul_rn(x,x), __fmul_rn(y,y)), __fmul_rn(z,z));
            #pragma unroll
            for (int j = 0; j < QPB; j++) {
                float dot = __fadd_rn(__fadd_rn(__fmul_rn(x,cx[j]), __fmul_rn(y,cy[j])), __fmul_rn(z,cz[j]));
                float d = __fsub_rn(__fadd_rn(sa[j], sn), __fmul_rn(2.0f, dot));
                if (d <= 0.04f) {
                    unsigned ub = __float_as_uint(d);
                    ub = ((int)ub < 0) ? ~ub : (ub | 0x80000000u);
                    int p = atomicAdd(&scnt[j], 1);
                    if (p < CAP) ck[j][p] = ((unsigned long long)ub << 32) | (unsigned)n;
                }
            }
        }
    }
    __syncthreads();
    if (t == 0) {
        int acc = 0;
        #pragma unroll
        for (int j = 0; j < QPB; j++) {
            soff[j] = acc;
            int c = scnt[j] < CAP ? scnt[j] : CAP;
            sm_m[j] = c < Kq ? c : Kq;
            acc += c;
        }
        soff[QPB] = acc;
    }
    __syncthreads();
    const int total = soff[QPB];
    for (int w = t; w < total; w += BT) {
        int j = 0;
        #pragma unroll
        for (int jj = 1; jj < QPB; jj++) j += (w >= soff[jj]);
        int p = w - soff[j];
        int cnt = soff[j+1] - soff[j];
        unsigned long long mk = ck[j][p];
        int r = 0;
        for (int i = 0; i < cnt; i++) r += (ck[j][i] < mk);
        if (r < Kq) ssel[j][r] = (int)(unsigned)mk;
    }
    __syncthreads();
    if (t < QPB*Kq) {
        int j = t >> 5, k = t & 31;
        g_grp[(q0+j)*Kq + k] = ssel[j][k < sm_m[j] ? k : 0];
    }
}

// ---------------- point-feature GEMM (FFMA2; coalesced W fill, padded Wt) ----------------
__global__ void __launch_bounds__(128) k_pf(const float* __restrict__ points,
                                            const float* __restrict__ W0) {
    extern __shared__ float sm[];
    float* xs = sm;                   // [64][XS_PAD]
    float* Wt = sm + 64*XS_PAD;       // [64][WP1]
    const int t = threadIdx.x;
    const int blk = blockIdx.x;
    // coalesced: consecutive i -> consecutive W0 addresses within a row
    for (int i = t; i < 64*64; i += 128) {
        int o = i >> 6, c = i & 63;
        Wt[c*WP1 + o] = W0[o*67 + 3 + c];
    }
    const float4* pts4 = (const float4*)points;
    #pragma unroll
    for (int jj = 0; jj < 16; jj++) {
        int idx = t + jj*128;
        int r = idx >> 4, c4 = idx & 15;
        float4 v = pts4[(size_t)(blk*128 + r)*16 + c4];
        xs[(4*c4+0)*XS_PAD + r] = v.x;
        xs[(4*c4+1)*XS_PAD + r] = v.y;
        xs[(4*c4+2)*XS_PAD + r] = v.z;
        xs[(4*c4+3)*XS_PAD + r] = v.w;
    }
    __syncthreads();
    const int r0 = (t & 15)*8, o0 = (t >> 4)*8;
    unsigned long long acc2[8][4];
    #pragma unroll
    for (int i = 0; i < 8; i++)
        #pragma unroll
        for (int j = 0; j < 4; j++) acc2[i][j] = 0ull;
    for (int c = 0; c < 64; c++) {
        float4 xa = *(const float4*)&xs[c*XS_PAD + r0];
        float4 xc = *(const float4*)&xs[c*XS_PAD + r0 + 4];
        ulonglong2 wA = *(const ulonglong2*)&Wt[c*WP1 + o0];
        ulonglong2 wB = *(const ulonglong2*)&Wt[c*WP1 + o0 + 4];
        unsigned long long wp[4] = {wA.x, wA.y, wB.x, wB.y};
        float xr[8] = {xa.x,xa.y,xa.z,xa.w,xc.x,xc.y,xc.z,xc.w};
        unsigned long long xp[8];
        #pragma unroll
        for (int i = 0; i < 8; i++) PACK2(xp[i], xr[i], xr[i]);
        #pragma unroll
        for (int i = 0; i < 8; i++)
            #pragma unroll
            for (int j = 0; j < 4; j++) FMA2(acc2[i][j], xp[i], wp[j]);
    }
    #pragma unroll
    for (int i = 0; i < 8; i++) {
        size_t base = ((size_t)(blk*128 + r0 + i))*64 + o0;
        *(ulonglong2*)&g_pf[base]   = make_ulonglong2(acc2[i][0], acc2[i][1]);
        *(ulonglong2*)&g_pf[base+4] = make_ulonglong2(acc2[i][2], acc2[i][3]);
    }
}

// ---------------- layer0 stats: vectorized gather ----------------
__global__ void __launch_bounds__(256) k_l0stats(const float* __restrict__ xyz,
                                                 const float* __restrict__ W0,
                                                 const float* __restrict__ b0) {
    __shared__ int   sgp[256];
    __shared__ float sdx[256], sdy[256], sdz[256];
    __shared__ float swx[64], swy[64], swz[64], sb[64];
    __shared__ float ps[64][17], pq[64][17];
    const int t = threadIdx.x;
    const int blk = blockIdx.x;
    if (t < 64) {
        swx[t] = W0[t*67+0]; swy[t] = W0[t*67+1]; swz[t] = W0[t*67+2]; sb[t] = b0[t];
    }
    {
        int R = blk*256 + t;
        int q = R >> 5, b = q >> 10;
        int gp = b*Nq + g_grp[R];
        sgp[t] = gp;
        sdx[t] = __fsub_rn(xyz[gp*3+0], g_newxyz[3*q+0]);
        sdy[t] = __fsub_rn(xyz[gp*3+1], g_newxyz[3*q+1]);
        sdz[t] = __fsub_rn(xyz[gp*3+2], g_newxyz[3*q+2]);
    }
    __syncthreads();
    const int cg = t & 15, rg = t >> 4;
    const int c0 = cg*4;
    float wx[4], wy[4], wz[4], bb[4];
    #pragma unroll
    for (int k = 0; k < 4; k++) { wx[k]=swx[c0+k]; wy[k]=swy[c0+k]; wz[k]=swz[c0+k]; bb[k]=sb[c0+k]; }
    float s[4] = {0,0,0,0}, s2[4] = {0,0,0,0};
    const float4* pf4 = (const float4*)g_pf;
    #pragma unroll 4
    for (int rr = 0; rr < 16; rr++) {
        int r = rg*16 + rr;
        float4 p = pf4[(size_t)sgp[r]*16 + cg];
        float dx = sdx[r], dy = sdy[r], dz = sdz[r];
        float pv[4] = {p.x, p.y, p.z, p.w};
        #pragma unroll
        for (int k = 0; k < 4; k++) {
            float y = pv[k] + fmaf(dx, wx[k], fmaf(dy, wy[k], fmaf(dz, wz[k], bb[k])));
            s[k] += y; s2[k] = fmaf(y, y, s2[k]);
        }
    }
    #pragma unroll
    for (int k = 0; k < 4; k++) { ps[c0+k][rg] = s[k]; pq[c0+k][rg] = s2[k]; }
    __syncthreads();
    if (t < 64) {
        double S = 0.0, Q = 0.0;
        #pragma unroll
        for (int g = 0; g < 16; g++) { S += (double)ps[t][g]; Q += (double)pq[t][g]; }
        g_part[(size_t)t*8192 + blk]       = S;
        g_part[(size_t)(128+t)*8192 + blk] = Q;
    }
}

// ---------------- BN finalize ----------------
__global__ void __launch_bounds__(256) k_fin(const float* __restrict__ ga,
                                             const float* __restrict__ be,
                                             int off, int nblk) {
    const int ch = blockIdx.x;
    const int t = threadIdx.x;
    double s = 0.0, s2 = 0.0;
    const double* p0 = g_part + (size_t)ch*8192;
    const double* p1 = g_part + (size_t)(128+ch)*8192;
    for (int i = t; i < nblk; i += 256) { s += p0[i]; s2 += p1[i]; }
    __shared__ double sh[256], sh2[256];
    sh[t] = s; sh2[t] = s2; __syncthreads();
    for (int o = 128; o; o >>= 1) {
        if (t < o) { sh[t] += sh[t+o]; sh2[t] += sh2[t+o]; }
        __syncthreads();
    }
    if (t == 0) {
        double mu  = sh[0]  / (double)NEq;
        double var = sh2[0] / (double)NEq - mu*mu;
        if (var < 0.0) var = 0.0;
        double sc = (double)ga[ch] / sqrt(var + 1e-5);
        g_scale[off+ch] = (float)sc;
        g_shift[off+ch] = (float)((double)be[ch] - mu*sc);
    }
}

// ---------------- layer1 (FFMA2; coalesced W fill, padded Wt) ----------------
__global__ void __launch_bounds__(128) k_layer1(const float* __restrict__ xyz,
                                                const float* __restrict__ W0,
                                                const float* __restrict__ b0,
                                                const float* __restrict__ W1,
                                                const float* __restrict__ b1) {
    extern __shared__ float sm[];
    float* xs  = sm;                   // [64][XS_PAD]
    float* Wt  = sm + 64*XS_PAD;       // [64][WP1]
    float* swx = Wt + 64*WP1;
    float* swy = swx + 64; float* swz = swy + 64; float* sb = swz + 64;
    float* ssc = sb + 64;  float* ssh = ssc + 64;
    const int t = threadIdx.x;
    const int blk = blockIdx.x;
    for (int i = t; i < 64*64; i += 128) {
        int o = i >> 6, c = i & 63;
        Wt[c*WP1 + o] = W1[i];               // W1 row-major: coalesced
    }
    if (t < 64) {
        swx[t] = W0[t*67+0]; swy[t] = W0[t*67+1]; swz[t] = W0[t*67+2];
        sb[t] = b0[t]; ssc[t] = g_scale[t]; ssh[t] = g_shift[t];
    }
    int R = blk*128 + t;
    int q = R >> 5, b = q >> 10;
    int gp = b*Nq + g_grp[R];
    float dx = __fsub_rn(xyz[gp*3+0], g_newxyz[3*q+0]);
    float dy = __fsub_rn(xyz[gp*3+1], g_newxyz[3*q+1]);
    float dz = __fsub_rn(xyz[gp*3+2], g_newxyz[3*q+2]);
    __syncthreads();
    const float4* pfv4 = (const float4*)g_pf;
    #pragma unroll
    for (int c4 = 0; c4 < 16; c4++) {
        float4 p = pfv4[(size_t)gp*16 + c4];
        float pv[4] = {p.x, p.y, p.z, p.w};
        #pragma unroll
        for (int k2 = 0; k2 < 4; k2++) {
            int c = c4*4 + k2;
            float y = pv[k2] + fmaf(dx, swx[c], fmaf(dy, swy[c], fmaf(dz, swz[c], sb[c])));
            xs[c*XS_PAD + t] = fmaxf(fmaf(ssc[c], y, ssh[c]), 0.0f);
        }
    }
    __syncthreads();
    const int r0 = (t & 15)*8, o0 = (t >> 4)*8;
    unsigned long long acc2[8][4];
    {
        ulonglong2 bA = *(const ulonglong2*)&b1[o0];
        ulonglong2 bB = *(const ulonglong2*)&b1[o0+4];
        unsigned long long bp[4] = {bA.x, bA.y, bB.x, bB.y};
        #pragma unroll
        for (int i = 0; i < 8; i++)
            #pragma unroll
            for (int j = 0; j < 4; j++) acc2[i][j] = bp[j];
    }
    for (int c = 0; c < 64; c++) {
        float4 xa = *(const float4*)&xs[c*XS_PAD + r0];
        float4 xc = *(const float4*)&xs[c*XS_PAD + r0 + 4];
        ulonglong2 wA = *(const ulonglong2*)&Wt[c*WP1 + o0];
        ulonglong2 wB = *(const ulonglong2*)&Wt[c*WP1 + o0 + 4];
        unsigned long long wp[4] = {wA.x, wA.y, wB.x, wB.y};
        float xr[8] = {xa.x,xa.y,xa.z,xa.w,xc.x,xc.y,xc.z,xc.w};
        unsigned long long xp[8];
        #pragma unroll
        for (int i = 0; i < 8; i++) PACK2(xp[i], xr[i], xr[i]);
        #pragma unroll
        for (int i = 0; i < 8; i++)
            #pragma unroll
            for (int j = 0; j < 4; j++) FMA2(acc2[i][j], xp[i], wp[j]);
    }
    #pragma unroll
    for (int i = 0; i < 8; i++) {
        size_t base = ((size_t)(blk*128 + r0 + i))*64 + o0;
        *(ulonglong2*)&g_y1[base]   = make_ulonglong2(acc2[i][0], acc2[i][1]);
        *(ulonglong2*)&g_y1[base+4] = make_ulonglong2(acc2[i][2], acc2[i][3]);
    }
    #pragma unroll
    for (int jp = 0; jp < 4; jp++) {
        float s0 = 0.0f, q0s = 0.0f, s1 = 0.0f, q1s = 0.0f;
        #pragma unroll
        for (int i = 0; i < 8; i++) {
            float a0, a1; UNPACK2(a0, a1, acc2[i][jp]);
            s0 += a0; q0s = fmaf(a0, a0, q0s);
            s1 += a1; q1s = fmaf(a1, a1, q1s);
        }
        #pragma unroll
        for (int off = 8; off; off >>= 1) {
            s0  += __shfl_down_sync(0xffffffffu, s0,  off, 16);
            q0s += __shfl_down_sync(0xffffffffu, q0s, off, 16);
            s1  += __shfl_down_sync(0xffffffffu, s1,  off, 16);
            q1s += __shfl_down_sync(0xffffffffu, q1s, off, 16);
        }
        if ((t & 15) == 0) {
            g_part[(size_t)(o0+2*jp)*8192 + blk]       = (double)s0;
            g_part[(size_t)(128+o0+2*jp)*8192 + blk]   = (double)q0s;
            g_part[(size_t)(o0+2*jp+1)*8192 + blk]     = (double)s1;
            g_part[(size_t)(128+o0+2*jp+1)*8192 + blk] = (double)q1s;
        }
    }
}

// ---------------- layer2 (FFMA2; coalesced W fill, padded Wt) ----------------
__global__ void __launch_bounds__(256, 2) k_layer2(const float* __restrict__ W2,
                                                   const float* __restrict__ b2) {
    extern __shared__ float sm[];
    float* xs  = sm;                   // [64][XS_PAD]
    float* Wt  = sm + 64*XS_PAD;       // [64][WP2]
    float* ssc = Wt + 64*WP2;
    float* ssh = ssc + 64;
    const int t = threadIdx.x;
    const int blk = blockIdx.x;
    for (int i = t; i < 128*64; i += 256) {
        int o = i >> 6, c = i & 63;
        Wt[c*WP2 + o] = W2[i];               // W2 row-major: coalesced
    }
    if (t < 64) { ssc[t] = g_scale[128+t]; ssh[t] = g_shift[128+t]; }
    __syncthreads();
    const float4* y1v = (const float4*)g_y1;
    #pragma unroll
    for (int jj = 0; jj < 8; jj++) {
        int idx = t + jj*256;
        int r = idx >> 4, c4 = idx & 15;
        float4 v = y1v[(size_t)(blk*128 + r)*16 + c4];
        float pv[4] = {v.x, v.y, v.z, v.w};
        #pragma unroll
        for (int k2 = 0; k2 < 4; k2++) {
            int c = c4*4 + k2;
            xs[c*XS_PAD + r] = fmaxf(fmaf(ssc[c], pv[k2], ssh[c]), 0.0f);
        }
    }
    __syncthreads();
    const int r0 = (t & 15)*8, o0 = (t >> 4)*8;
    unsigned long long acc2[8][4];
    {
        ulonglong2 bA = *(const ulonglong2*)&b2[o0];
        ulonglong2 bB = *(const ulonglong2*)&b2[o0+4];
        unsigned long long bp[4] = {bA.x, bA.y, bB.x, bB.y};
        #pragma unroll
        for (int i = 0; i < 8; i++)
            #pragma unroll
            for (int j = 0; j < 4; j++) acc2[i][j] = bp[j];
    }
    for (int c = 0; c < 64; c++) {
        float4 xa = *(const float4*)&xs[c*XS_PAD + r0];
        float4 xc = *(const float4*)&xs[c*XS_PAD + r0 + 4];
        ulonglong2 wA = *(const ulonglong2*)&Wt[c*WP2 + o0];
        ulonglong2 wB = *(const ulonglong2*)&Wt[c*WP2 + o0 + 4];
        unsigned long long wp[4] = {wA.x, wA.y, wB.x, wB.y};
        float xr[8] = {xa.x,xa.y,xa.z,xa.w,xc.x,xc.y,xc.z,xc.w};
        unsigned long long xp[8];
        #pragma unroll
        for (int i = 0; i < 8; i++) PACK2(xp[i], xr[i], xr[i]);
        #pragma unroll
        for (int i = 0; i < 8; i++)
            #pragma unroll
            for (int j = 0; j < 4; j++) FMA2(acc2[i][j], xp[i], wp[j]);
    }
    #pragma unroll
    for (int jp = 0; jp < 4; jp++) {
        float a0, a1; UNPACK2(a0, a1, acc2[0][jp]);
        float s0 = a0, q0s = a0*a0, mx0 = a0, mn0 = a0;
        float s1 = a1, q1s = a1*a1, mx1 = a1, mn1 = a1;
        #pragma unroll
        for (int i = 1; i < 8; i++) {
            UNPACK2(a0, a1, acc2[i][jp]);
            s0 += a0; q0s = fmaf(a0, a0, q0s); mx0 = fmaxf(mx0, a0); mn0 = fminf(mn0, a0);
            s1 += a1; q1s = fmaf(a1, a1, q1s); mx1 = fmaxf(mx1, a1); mn1 = fminf(mn1, a1);
        }
        #pragma unroll
        for (int off = 8; off; off >>= 1) {
            s0  += __shfl_down_sync(0xffffffffu, s0,  off, 16);
            q0s += __shfl_down_sync(0xffffffffu, q0s, off, 16);
            s1  += __shfl_down_sync(0xffffffffu, s1,  off, 16);
            q1s += __shfl_down_sync(0xffffffffu, q1s, off, 16);
        }
        if ((t & 15) == 0) {
            g_part[(size_t)(o0+2*jp)*8192 + blk]       = (double)s0;
            g_part[(size_t)(128+o0+2*jp)*8192 + blk]   = (double)q0s;
            g_part[(size_t)(o0+2*jp+1)*8192 + blk]     = (double)s1;
            g_part[(size_t)(128+o0+2*jp+1)*8192 + blk] = (double)q1s;
        }
        #pragma unroll
        for (int off = 2; off; off >>= 1) {
            mx0 = fmaxf(mx0, __shfl_down_sync(0xffffffffu, mx0, off, 4));
            mn0 = fminf(mn0, __shfl_down_sync(0xffffffffu, mn0, off, 4));
            mx1 = fmaxf(mx1, __shfl_down_sync(0xffffffffu, mx1, off, 4));
            mn1 = fminf(mn1, __shfl_down_sync(0xffffffffu, mn1, off, 4));
        }
        if ((t & 3) == 0) {
            int qg = blk*4 + ((t & 15) >> 2);
            g_maxv[(size_t)qg*128 + o0 + 2*jp]     = mx0;
            g_minv[(size_t)qg*128 + o0 + 2*jp]     = mn0;
            g_maxv[(size_t)qg*128 + o0 + 2*jp + 1] = mx1;
            g_minv[(size_t)qg*128 + o0 + 2*jp + 1] = mn1;
        }
    }
}

// ---------------- final: BN2+ReLU fused max-pool from min/max ----------------
__global__ void __launch_bounds__(256) k_maxpool(float* __restrict__ out) {
    int i = blockIdx.x*256 + threadIdx.x;
    int o = i & 127;
    float sc = g_scale[256+o], sh = g_shift[256+o];
    float v = (sc >= 0.0f) ? g_maxv[i] : g_minv[i];
    out[OUT_PTS + i] = fmaxf(fmaf(sc, v, sh), 0.0f);
}

// ---------------- launch (sequential) ----------------
extern "C" void kernel_launch(void* const* d_in, const int* in_sizes, int n_in,
                              void* d_out, int out_size) {
    (void)in_sizes; (void)n_in; (void)out_size;
    const float* xyz    = (const float*)d_in[0];
    const float* points = (const float*)d_in[1];
    const float* W0  = (const float*)d_in[2];
    const float* b0  = (const float*)d_in[3];
    const float* g0  = (const float*)d_in[4];
    const float* bt0 = (const float*)d_in[5];
    const float* W1  = (const float*)d_in[6];
    const float* b1  = (const float*)d_in[7];
    const float* g1  = (const float*)d_in[8];
    const float* bt1 = (const float*)d_in[9];
    const float* W2  = (const float*)d_in[10];
    const float* b2  = (const float*)d_in[11];
    const float* g2  = (const float*)d_in[12];
    const float* bt2 = (const float*)d_in[13];
    float* out = (float*)d_out;

    const int SM_PF = (64*XS_PAD + 64*WP1) * 4;
    const int SM_L1 = (64*XS_PAD + 64*WP1 + 6*64) * 4;
    const int SM_L2 = (64*XS_PAD + 64*WP2 + 2*64) * 4;
    cudaFuncSetAttribute(k_pf,     cudaFuncAttributeMaxDynamicSharedMemorySize, SM_PF);
    cudaFuncSetAttribute(k_layer1, cudaFuncAttributeMaxDynamicSharedMemorySize, SM_L1);
    cudaFuncSetAttribute(k_layer2, cudaFuncAttributeMaxDynamicSharedMemorySize, SM_L2);

    k_pf<<<NP/128, 128, SM_PF>>>(points, W0);
    k_fps<<<Bq, 512>>>(xyz, out);
    k_ball<<<NQ/QPB, BT>>>(xyz);

    k_l0stats<<<NEq/256, 256>>>(xyz, W0, b0);
    k_fin<<<64, 256>>>(g0, bt0, 0, NEq/256);
    k_layer1<<<NEq/128, 128, SM_L1>>>(xyz, W0, b0, W1, b1);
    k_fin<<<64, 256>>>(g1, bt1, 128, NEq/128);
    k_layer2<<<NEq/128, 256, SM_L2>>>(W2, b2);
    k_fin<<<128, 256>>>(g2, bt2, 256, NEq/128);
    k_maxpool<<<NQ*128/256, 256>>>(out);
}

// round 16
// speedup vs baseline: 1.3699x; 1.0001x over previous
#include <cuda_runtime.h>
#include <cstdint>

#define Bq 16
#define Nq 4096
#define Sq 1024
#define Kq 32
#define NQ (Bq*Sq)          // 16384 queries
#define NP (Bq*Nq)          // 65536 points
#define NEq (NQ*Kq)         // 524288 rows
#define OUT_PTS (NQ*3)
#define XS_PAD 132
#define WP1 68              // padded Wt stride for COUT=64  (272B rows, 16B-aligned)
#define WP2 132             // padded Wt stride for COUT=128 (528B rows, 16B-aligned)
#define QPB 4               // queries per ball block
#define CAP 768             // candidate cap per query (mean 137, sd ~12)
#define BT 256              // ball block threads

// packed fp32x2 helpers (exact IEEE fp32 per lane; only add/mul/fma exist packed)
#define FMA2(d,a,b)   asm("fma.rn.f32x2 %0, %1, %2, %0;" : "+l"(d) : "l"(a), "l"(b))
#define ADD2(d,a,b)   asm("add.rn.f32x2 %0, %1, %2;" : "=l"(d) : "l"(a), "l"(b))
#define MUL2(d,a,b)   asm("mul.rn.f32x2 %0, %1, %2;" : "=l"(d) : "l"(a), "l"(b))
#define PACK2(d,x,y)  asm("mov.b64 %0, {%1, %2};" : "=l"(d) : "f"(x), "f"(y))
#define UNPACK2(x,y,d) asm("mov.b64 {%0, %1}, %2;" : "=f"(x), "=f"(y) : "l"(d))

// ---------------- scratch ----------------
__device__ float  g_newxyz[NQ*3];
__device__ int    g_grp[NEq];
__device__ float  g_pf[(size_t)NP*64];        // point features (layer0 w/o geom), 16MB
__device__ float  g_y1[(size_t)NEq*64];       // layer1 pre-BN output, 134MB
__device__ float  g_maxv[(size_t)NQ*128];
__device__ float  g_minv[(size_t)NQ*128];
__device__ double g_part[(size_t)256*8192];
__device__ float  g_scale[384];
__device__ float  g_shift[384];

// ---------------- FPS: smem xyz cache, packed body, REDUX two-level tail ----------------
__global__ void __launch_bounds__(512) k_fps(const float* __restrict__ xyz,
                                             float* __restrict__ out) {
    const int b = blockIdx.x;
    const int t = threadIdx.x;
    const int lane = t & 31, wid = t >> 5;
    const float* xb = xyz + b*Nq*3;
    __shared__ float sxy[Nq*3];                 // 48KB: whole batch resident in smem
    __shared__ unsigned swv[2][16];             // double-buffered warp value partials
    __shared__ int      swi[2][16];             // warp index partials
    {
        const float4* src = (const float4*)xb;
        float4* dst = (float4*)sxy;
        #pragma unroll
        for (int i = 0; i < (Nq*3/4)/512; i++) dst[t + i*512] = src[t + i*512];
    }
    __syncthreads();
    unsigned long long px2[4], py2[4], pz2[4];
    float dd[8];
    #pragma unroll
    for (int j = 0; j < 4; j++) {
        int p0 = t + (2*j)*512, p1 = p0 + 512;
        PACK2(px2[j], sxy[3*p0],   sxy[3*p1]);
        PACK2(py2[j], sxy[3*p0+1], sxy[3*p1+1]);
        PACK2(pz2[j], sxy[3*p0+2], sxy[3*p1+2]);
        dd[2*j] = 1e10f; dd[2*j+1] = 1e10f;
    }
    int far = 0;
    for (int i = 0; i < Sq; i++) {
        float cx = sxy[3*far], cy = sxy[3*far+1], cz = sxy[3*far+2];
        if (t == 0) {
            int o = (b*Sq + i)*3;
            g_newxyz[o] = cx; g_newxyz[o+1] = cy; g_newxyz[o+2] = cz;
            out[o] = cx; out[o+1] = cy; out[o+2] = cz;
        }
        float ncx = -cx, ncy = -cy, ncz = -cz;   // x - c == x + (-c) exactly
        unsigned long long ncx2, ncy2, ncz2;
        PACK2(ncx2, ncx, ncx); PACK2(ncy2, ncy, ncy); PACK2(ncz2, ncz, ncz);
        float bv = -1.0f; int bi = 0;
        #pragma unroll
        for (int j = 0; j < 4; j++) {
            unsigned long long dx, dy, dz, sx, sy, sz, sA, sB;
            ADD2(dx, px2[j], ncx2);
            ADD2(dy, py2[j], ncy2);
            ADD2(dz, pz2[j], ncz2);
            MUL2(sx, dx, dx);
            MUL2(sy, dy, dy);
            MUL2(sz, dz, dz);
            ADD2(sA, sx, sy);
            ADD2(sB, sA, sz);        // exact reference fold per lane
            float d0, d1; UNPACK2(d0, d1, sB);
            float nd0 = fminf(dd[2*j], d0);   dd[2*j]   = nd0;
            if (nd0 > bv) { bv = nd0; bi = t + (2*j)*512; }
            float nd1 = fminf(dd[2*j+1], d1); dd[2*j+1] = nd1;
            if (nd1 > bv) { bv = nd1; bi = t + (2*j+1)*512; }
        }
        unsigned vb = __float_as_uint(bv);
        unsigned vmax = __reduce_max_sync(0xffffffffu, vb);
        int cand = (vb == vmax) ? bi : 0x7fffffff;
        int bimin = __reduce_min_sync(0xffffffffu, cand);
        const int par = i & 1;
        if (lane == 0) { swv[par][wid] = vmax; swi[par][wid] = bimin; }
        __syncthreads();
        unsigned v2 = swv[par][lane & 15];
        int i2 = swi[par][lane & 15];
        unsigned gmax = __reduce_max_sync(0xffffffffu, v2);
        int c2 = (v2 == gmax) ? i2 : 0x7fffffff;
        far = __reduce_min_sync(0xffffffffu, c2);
    }
}

// ---------------- ball query: vectorized sweep, flattened rank ----------------
__global__ void __launch_bounds__(BT) k_ball(const float* __restrict__ xyz) {
    const int blk = blockIdx.x;
    const int q0 = blk * QPB;
    const int b = q0 >> 10;
    const int t = threadIdx.x;
    __shared__ unsigned long long ck[QPB][CAP];
    __shared__ int scnt[QPB];
    __shared__ int sm_m[QPB];
    __shared__ int soff[QPB+1];
    __shared__ int ssel[QPB][Kq];
    if (t < QPB) scnt[t] = 0;
    __syncthreads();
    float cx[QPB], cy[QPB], cz[QPB], sa[QPB];
    #pragma unroll
    for (int j = 0; j < QPB; j++) {
        cx[j] = g_newxyz[3*(q0+j)]; cy[j] = g_newxyz[3*(q0+j)+1]; cz[j] = g_newxyz[3*(q0+j)+2];
        sa[j] = __fadd_rn(__fadd_rn(__fmul_rn(cx[j],cx[j]), __fmul_rn(cy[j],cy[j])), __fmul_rn(cz[j],cz[j]));
    }
    const float4* xb4 = (const float4*)(xyz + (size_t)b*Nq*3);
    #pragma unroll
    for (int k = 0; k < Nq/(4*BT); k++) {
        int m = t + k*BT;
        float4 f0 = xb4[3*m], f1 = xb4[3*m+1], f2 = xb4[3*m+2];
        float gx[4] = {f0.x, f0.w, f1.z, f2.y};
        float gy[4] = {f0.y, f1.x, f1.w, f2.z};
        float gz[4] = {f0.z, f1.y, f2.x, f2.w};
        #pragma unroll
        for (int u = 0; u < 4; u++) {
            int n = 4*m + u;
            float x = gx[u], y = gy[u], z = gz[u];
            float sn = __fadd_rn(__fadd_rn(__fmul_rn(x,x), __fmul_rn(y,y)), __fmul_rn(z,z));
            #pragma unroll
            for (int j = 0; j < QPB; j++) {
                float dot = __fadd_rn(__fadd_rn(__fmul_rn(x,cx[j]), __fmul_rn(y,cy[j])), __fmul_rn(z,cz[j]));
                float d = __fsub_rn(__fadd_rn(sa[j], sn), __fmul_rn(2.0f, dot));
                if (d <= 0.04f) {
                    unsigned ub = __float_as_uint(d);
                    ub = ((int)ub < 0) ? ~ub : (ub | 0x80000000u);
                    int p = atomicAdd(&scnt[j], 1);
                    if (p < CAP) ck[j][p] = ((unsigned long long)ub << 32) | (unsigned)n;
                }
            }
        }
    }
    __syncthreads();
    if (t == 0) {
        int acc = 0;
        #pragma unroll
        for (int j = 0; j < QPB; j++) {
            soff[j] = acc;
            int c = scnt[j] < CAP ? scnt[j] : CAP;
            sm_m[j] = c < Kq ? c : Kq;
            acc += c;
        }
        soff[QPB] = acc;
    }
    __syncthreads();
    const int total = soff[QPB];
    for (int w = t; w < total; w += BT) {
        int j = 0;
        #pragma unroll
        for (int jj = 1; jj < QPB; jj++) j += (w >= soff[jj]);
        int p = w - soff[j];
        int cnt = soff[j+1] - soff[j];
        unsigned long long mk = ck[j][p];
        int r = 0;
        for (int i = 0; i < cnt; i++) r += (ck[j][i] < mk);
        if (r < Kq) ssel[j][r] = (int)(unsigned)mk;
    }
    __syncthreads();
    if (t < QPB*Kq) {
        int j = t >> 5, k = t & 31;
        g_grp[(q0+j)*Kq + k] = ssel[j][k < sm_m[j] ? k : 0];
    }
}

// ---------------- point-feature GEMM (FFMA2; coalesced W fill, padded Wt) ----------------
__global__ void __launch_bounds__(128) k_pf(const float* __restrict__ points,
                                            const float* __restrict__ W0) {
    extern __shared__ float sm[];
    float* xs = sm;                   // [64][XS_PAD]
    float* Wt = sm + 64*XS_PAD;       // [64][WP1]
    const int t = threadIdx.x;
    const int blk = blockIdx.x;
    for (int i = t; i < 64*64; i += 128) {
        int o = i >> 6, c = i & 63;
        Wt[c*WP1 + o] = W0[o*67 + 3 + c];
    }
    const float4* pts4 = (const float4*)points;
    #pragma unroll
    for (int jj = 0; jj < 16; jj++) {
        int idx = t + jj*128;
        int r = idx >> 4, c4 = idx & 15;
        float4 v = pts4[(size_t)(blk*128 + r)*16 + c4];
        xs[(4*c4+0)*XS_PAD + r] = v.x;
        xs[(4*c4+1)*XS_PAD + r] = v.y;
        xs[(4*c4+2)*XS_PAD + r] = v.z;
        xs[(4*c4+3)*XS_PAD + r] = v.w;
    }
    __syncthreads();
    const int r0 = (t & 15)*8, o0 = (t >> 4)*8;
    unsigned long long acc2[8][4];
    #pragma unroll
    for (int i = 0; i < 8; i++)
        #pragma unroll
        for (int j = 0; j < 4; j++) acc2[i][j] = 0ull;
    for (int c = 0; c < 64; c++) {
        float4 xa = *(const float4*)&xs[c*XS_PAD + r0];
        float4 xc = *(const float4*)&xs[c*XS_PAD + r0 + 4];
        ulonglong2 wA = *(const ulonglong2*)&Wt[c*WP1 + o0];
        ulonglong2 wB = *(const ulonglong2*)&Wt[c*WP1 + o0 + 4];
        unsigned long long wp[4] = {wA.x, wA.y, wB.x, wB.y};
        float xr[8] = {xa.x,xa.y,xa.z,xa.w,xc.x,xc.y,xc.z,xc.w};
        unsigned long long xp[8];
        #pragma unroll
        for (int i = 0; i < 8; i++) PACK2(xp[i], xr[i], xr[i]);
        #pragma unroll
        for (int i = 0; i < 8; i++)
            #pragma unroll
            for (int j = 0; j < 4; j++) FMA2(acc2[i][j], xp[i], wp[j]);
    }
    #pragma unroll
    for (int i = 0; i < 8; i++) {
        size_t base = ((size_t)(blk*128 + r0 + i))*64 + o0;
        *(ulonglong2*)&g_pf[base]   = make_ulonglong2(acc2[i][0], acc2[i][1]);
        *(ulonglong2*)&g_pf[base+4] = make_ulonglong2(acc2[i][2], acc2[i][3]);
    }
}

// ---------------- layer0 stats: fully-unrolled gather (MLP=16) ----------------
__global__ void __launch_bounds__(256) k_l0stats(const float* __restrict__ xyz,
                                                 const float* __restrict__ W0,
                                                 const float* __restrict__ b0) {
    __shared__ int   sgp[256];
    __shared__ float sdx[256], sdy[256], sdz[256];
    __shared__ float swx[64], swy[64], swz[64], sb[64];
    __shared__ float ps[64][17], pq[64][17];
    const int t = threadIdx.x;
    const int blk = blockIdx.x;
    if (t < 64) {
        swx[t] = W0[t*67+0]; swy[t] = W0[t*67+1]; swz[t] = W0[t*67+2]; sb[t] = b0[t];
    }
    {
        int R = blk*256 + t;
        int q = R >> 5, b = q >> 10;
        int gp = b*Nq + g_grp[R];
        sgp[t] = gp;
        sdx[t] = __fsub_rn(xyz[gp*3+0], g_newxyz[3*q+0]);
        sdy[t] = __fsub_rn(xyz[gp*3+1], g_newxyz[3*q+1]);
        sdz[t] = __fsub_rn(xyz[gp*3+2], g_newxyz[3*q+2]);
    }
    __syncthreads();
    const int cg = t & 15, rg = t >> 4;
    const int c0 = cg*4;
    float wx[4], wy[4], wz[4], bb[4];
    #pragma unroll
    for (int k = 0; k < 4; k++) { wx[k]=swx[c0+k]; wy[k]=swy[c0+k]; wz[k]=swz[c0+k]; bb[k]=sb[c0+k]; }
    float s[4] = {0,0,0,0}, s2[4] = {0,0,0,0};
    const float4* pf4 = (const float4*)g_pf;
    // batch ALL 16 gathered loads up front: MLP=16 hides DRAM/L2 latency
    float4 pv16[16];
    #pragma unroll
    for (int rr = 0; rr < 16; rr++) {
        pv16[rr] = pf4[(size_t)sgp[rg*16 + rr]*16 + cg];
    }
    #pragma unroll
    for (int rr = 0; rr < 16; rr++) {
        int r = rg*16 + rr;
        float dx = sdx[r], dy = sdy[r], dz = sdz[r];
        float pv[4] = {pv16[rr].x, pv16[rr].y, pv16[rr].z, pv16[rr].w};
        #pragma unroll
        for (int k = 0; k < 4; k++) {
            float y = pv[k] + fmaf(dx, wx[k], fmaf(dy, wy[k], fmaf(dz, wz[k], bb[k])));
            s[k] += y; s2[k] = fmaf(y, y, s2[k]);
        }
    }
    #pragma unroll
    for (int k = 0; k < 4; k++) { ps[c0+k][rg] = s[k]; pq[c0+k][rg] = s2[k]; }
    __syncthreads();
    if (t < 64) {
        double S = 0.0, Q = 0.0;
        #pragma unroll
        for (int g = 0; g < 16; g++) { S += (double)ps[t][g]; Q += (double)pq[t][g]; }
        g_part[(size_t)t*8192 + blk]       = S;
        g_part[(size_t)(128+t)*8192 + blk] = Q;
    }
}

// ---------------- BN finalize ----------------
__global__ void __launch_bounds__(256) k_fin(const float* __restrict__ ga,
                                             const float* __restrict__ be,
                                             int off, int nblk) {
    const int ch = blockIdx.x;
    const int t = threadIdx.x;
    double s = 0.0, s2 = 0.0;
    const double* p0 = g_part + (size_t)ch*8192;
    const double* p1 = g_part + (size_t)(128+ch)*8192;
    for (int i = t; i < nblk; i += 256) { s += p0[i]; s2 += p1[i]; }
    __shared__ double sh[256], sh2[256];
    sh[t] = s; sh2[t] = s2; __syncthreads();
    for (int o = 128; o; o >>= 1) {
        if (t < o) { sh[t] += sh[t+o]; sh2[t] += sh2[t+o]; }
        __syncthreads();
    }
    if (t == 0) {
        double mu  = sh[0]  / (double)NEq;
        double var = sh2[0] / (double)NEq - mu*mu;
        if (var < 0.0) var = 0.0;
        double sc = (double)ga[ch] / sqrt(var + 1e-5);
        g_scale[off+ch] = (float)sc;
        g_shift[off+ch] = (float)((double)be[ch] - mu*sc);
    }
}

// ---------------- layer1 (FFMA2; coalesced W fill, padded Wt) ----------------
__global__ void __launch_bounds__(128) k_layer1(const float* __restrict__ xyz,
                                                const float* __restrict__ W0,
                                                const float* __restrict__ b0,
                                                const float* __restrict__ W1,
                                                const float* __restrict__ b1) {
    extern __shared__ float sm[];
    float* xs  = sm;                   // [64][XS_PAD]
    float* Wt  = sm + 64*XS_PAD;       // [64][WP1]
    float* swx = Wt + 64*WP1;
    float* swy = swx + 64; float* swz = swy + 64; float* sb = swz + 64;
    float* ssc = sb + 64;  float* ssh = ssc + 64;
    const int t = threadIdx.x;
    const int blk = blockIdx.x;
    for (int i = t; i < 64*64; i += 128) {
        int o = i >> 6, c = i & 63;
        Wt[c*WP1 + o] = W1[i];               // W1 row-major: coalesced
    }
    if (t < 64) {
        swx[t] = W0[t*67+0]; swy[t] = W0[t*67+1]; swz[t] = W0[t*67+2];
        sb[t] = b0[t]; ssc[t] = g_scale[t]; ssh[t] = g_shift[t];
    }
    int R = blk*128 + t;
    int q = R >> 5, b = q >> 10;
    int gp = b*Nq + g_grp[R];
    float dx = __fsub_rn(xyz[gp*3+0], g_newxyz[3*q+0]);
    float dy = __fsub_rn(xyz[gp*3+1], g_newxyz[3*q+1]);
    float dz = __fsub_rn(xyz[gp*3+2], g_newxyz[3*q+2]);
    __syncthreads();
    const float4* pfv4 = (const float4*)g_pf;
    #pragma unroll
    for (int c4 = 0; c4 < 16; c4++) {
        float4 p = pfv4[(size_t)gp*16 + c4];
        float pv[4] = {p.x, p.y, p.z, p.w};
        #pragma unroll
        for (int k2 = 0; k2 < 4; k2++) {
            int c = c4*4 + k2;
            float y = pv[k2] + fmaf(dx, swx[c], fmaf(dy, swy[c], fmaf(dz, swz[c], sb[c])));
            xs[c*XS_PAD + t] = fmaxf(fmaf(ssc[c], y, ssh[c]), 0.0f);
        }
    }
    __syncthreads();
    const int r0 = (t & 15)*8, o0 = (t >> 4)*8;
    unsigned long long acc2[8][4];
    {
        ulonglong2 bA = *(const ulonglong2*)&b1[o0];
        ulonglong2 bB = *(const ulonglong2*)&b1[o0+4];
        unsigned long long bp[4] = {bA.x, bA.y, bB.x, bB.y};
        #pragma unroll
        for (int i = 0; i < 8; i++)
            #pragma unroll
            for (int j = 0; j < 4; j++) acc2[i][j] = bp[j];
    }
    for (int c = 0; c < 64; c++) {
        float4 xa = *(const float4*)&xs[c*XS_PAD + r0];
        float4 xc = *(const float4*)&xs[c*XS_PAD + r0 + 4];
        ulonglong2 wA = *(const ulonglong2*)&Wt[c*WP1 + o0];
        ulonglong2 wB = *(const ulonglong2*)&Wt[c*WP1 + o0 + 4];
        unsigned long long wp[4] = {wA.x, wA.y, wB.x, wB.y};
        float xr[8] = {xa.x,xa.y,xa.z,xa.w,xc.x,xc.y,xc.z,xc.w};
        unsigned long long xp[8];
        #pragma unroll
        for (int i = 0; i < 8; i++) PACK2(xp[i], xr[i], xr[i]);
        #pragma unroll
        for (int i = 0; i < 8; i++)
            #pragma unroll
            for (int j = 0; j < 4; j++) FMA2(acc2[i][j], xp[i], wp[j]);
    }
    #pragma unroll
    for (int i = 0; i < 8; i++) {
        size_t base = ((size_t)(blk*128 + r0 + i))*64 + o0;
        *(ulonglong2*)&g_y1[base]   = make_ulonglong2(acc2[i][0], acc2[i][1]);
        *(ulonglong2*)&g_y1[base+4] = make_ulonglong2(acc2[i][2], acc2[i][3]);
    }
    #pragma unroll
    for (int jp = 0; jp < 4; jp++) {
        float s0 = 0.0f, q0s = 0.0f, s1 = 0.0f, q1s = 0.0f;
        #pragma unroll
        for (int i = 0; i < 8; i++) {
            float a0, a1; UNPACK2(a0, a1, acc2[i][jp]);
            s0 += a0; q0s = fmaf(a0, a0, q0s);
            s1 += a1; q1s = fmaf(a1, a1, q1s);
        }
        #pragma unroll
        for (int off = 8; off; off >>= 1) {
            s0  += __shfl_down_sync(0xffffffffu, s0,  off, 16);
            q0s += __shfl_down_sync(0xffffffffu, q0s, off, 16);
            s1  += __shfl_down_sync(0xffffffffu, s1,  off, 16);
            q1s += __shfl_down_sync(0xffffffffu, q1s, off, 16);
        }
        if ((t & 15) == 0) {
            g_part[(size_t)(o0+2*jp)*8192 + blk]       = (double)s0;
            g_part[(size_t)(128+o0+2*jp)*8192 + blk]   = (double)q0s;
            g_part[(size_t)(o0+2*jp+1)*8192 + blk]     = (double)s1;
            g_part[(size_t)(128+o0+2*jp+1)*8192 + blk] = (double)q1s;
        }
    }
}

// ---------------- layer2 (FFMA2; coalesced W fill, padded Wt) ----------------
__global__ void __launch_bounds__(256, 2) k_layer2(const float* __restrict__ W2,
                                                   const float* __restrict__ b2) {
    extern __shared__ float sm[];
    float* xs  = sm;                   // [64][XS_PAD]
    float* Wt  = sm + 64*XS_PAD;       // [64][WP2]
    float* ssc = Wt + 64*WP2;
    float* ssh = ssc + 64;
    const int t = threadIdx.x;
    const int blk = blockIdx.x;
    for (int i = t; i < 128*64; i += 256) {
        int o = i >> 6, c = i & 63;
        Wt[c*WP2 + o] = W2[i];               // W2 row-major: coalesced
    }
    if (t < 64) { ssc[t] = g_scale[128+t]; ssh[t] = g_shift[128+t]; }
    __syncthreads();
    const float4* y1v = (const float4*)g_y1;
    #pragma unroll
    for (int jj = 0; jj < 8; jj++) {
        int idx = t + jj*256;
        int r = idx >> 4, c4 = idx & 15;
        float4 v = y1v[(size_t)(blk*128 + r)*16 + c4];
        float pv[4] = {v.x, v.y, v.z, v.w};
        #pragma unroll
        for (int k2 = 0; k2 < 4; k2++) {
            int c = c4*4 + k2;
            xs[c*XS_PAD + r] = fmaxf(fmaf(ssc[c], pv[k2], ssh[c]), 0.0f);
        }
    }
    __syncthreads();
    const int r0 = (t & 15)*8, o0 = (t >> 4)*8;
    unsigned long long acc2[8][4];
    {
        ulonglong2 bA = *(const ulonglong2*)&b2[o0];
        ulonglong2 bB = *(const ulonglong2*)&b2[o0+4];
        unsigned long long bp[4] = {bA.x, bA.y, bB.x, bB.y};
        #pragma unroll
        for (int i = 0; i < 8; i++)
            #pragma unroll
            for (int j = 0; j < 4; j++) acc2[i][j] = bp[j];
    }
    for (int c = 0; c < 64; c++) {
        float4 xa = *(const float4*)&xs[c*XS_PAD + r0];
        float4 xc = *(const float4*)&xs[c*XS_PAD + r0 + 4];
        ulonglong2 wA = *(const ulonglong2*)&Wt[c*WP2 + o0];
        ulonglong2 wB = *(const ulonglong2*)&Wt[c*WP2 + o0 + 4];
        unsigned long long wp[4] = {wA.x, wA.y, wB.x, wB.y};
        float xr[8] = {xa.x,xa.y,xa.z,xa.w,xc.x,xc.y,xc.z,xc.w};
        unsigned long long xp[8];
        #pragma unroll
        for (int i = 0; i < 8; i++) PACK2(xp[i], xr[i], xr[i]);
        #pragma unroll
        for (int i = 0; i < 8; i++)
            #pragma unroll
            for (int j = 0; j < 4; j++) FMA2(acc2[i][j], xp[i], wp[j]);
    }
    #pragma unroll
    for (int jp = 0; jp < 4; jp++) {
        float a0, a1; UNPACK2(a0, a1, acc2[0][jp]);
        float s0 = a0, q0s = a0*a0, mx0 = a0, mn0 = a0;
        float s1 = a1, q1s = a1*a1, mx1 = a1, mn1 = a1;
        #pragma unroll
        for (int i = 1; i < 8; i++) {
            UNPACK2(a0, a1, acc2[i][jp]);
            s0 += a0; q0s = fmaf(a0, a0, q0s); mx0 = fmaxf(mx0, a0); mn0 = fminf(mn0, a0);
            s1 += a1; q1s = fmaf(a1, a1, q1s); mx1 = fmaxf(mx1, a1); mn1 = fminf(mn1, a1);
        }
        #pragma unroll
        for (int off = 8; off; off >>= 1) {
            s0  += __shfl_down_sync(0xffffffffu, s0,  off, 16);
            q0s += __shfl_down_sync(0xffffffffu, q0s, off, 16);
            s1  += __shfl_down_sync(0xffffffffu, s1,  off, 16);
            q1s += __shfl_down_sync(0xffffffffu, q1s, off, 16);
        }
        if ((t & 15) == 0) {
            g_part[(size_t)(o0+2*jp)*8192 + blk]       = (double)s0;
            g_part[(size_t)(128+o0+2*jp)*8192 + blk]   = (double)q0s;
            g_part[(size_t)(o0+2*jp+1)*8192 + blk]     = (double)s1;
            g_part[(size_t)(128+o0+2*jp+1)*8192 + blk] = (double)q1s;
        }
        #pragma unroll
        for (int off = 2; off; off >>= 1) {
            mx0 = fmaxf(mx0, __shfl_down_sync(0xffffffffu, mx0, off, 4));
            mn0 = fminf(mn0, __shfl_down_sync(0xffffffffu, mn0, off, 4));
            mx1 = fmaxf(mx1, __shfl_down_sync(0xffffffffu, mx1, off, 4));
            mn1 = fminf(mn1, __shfl_down_sync(0xffffffffu, mn1, off, 4));
        }
        if ((t & 3) == 0) {
            int qg = blk*4 + ((t & 15) >> 2);
            g_maxv[(size_t)qg*128 + o0 + 2*jp]     = mx0;
            g_minv[(size_t)qg*128 + o0 + 2*jp]     = mn0;
            g_maxv[(size_t)qg*128 + o0 + 2*jp + 1] = mx1;
            g_minv[(size_t)qg*128 + o0 + 2*jp + 1] = mn1;
        }
    }
}

// ---------------- final: BN2+ReLU fused max-pool from min/max ----------------
__global__ void __launch_bounds__(256) k_maxpool(float* __restrict__ out) {
    int i = blockIdx.x*256 + threadIdx.x;
    int o = i & 127;
    float sc = g_scale[256+o], sh = g_shift[256+o];
    float v = (sc >= 0.0f) ? g_maxv[i] : g_minv[i];
    out[OUT_PTS + i] = fmaxf(fmaf(sc, v, sh), 0.0f);
}

// ---------------- launch (sequential) ----------------
extern "C" void kernel_launch(void* const* d_in, const int* in_sizes, int n_in,
                              void* d_out, int out_size) {
    (void)in_sizes; (void)n_in; (void)out_size;
    const float* xyz    = (const float*)d_in[0];
    const float* points = (const float*)d_in[1];
    const float* W0  = (const float*)d_in[2];
    const float* b0  = (const float*)d_in[3];
    const float* g0  = (const float*)d_in[4];
    const float* bt0 = (const float*)d_in[5];
    const float* W1  = (const float*)d_in[6];
    const float* b1  = (const float*)d_in[7];
    const float* g1  = (const float*)d_in[8];
    const float* bt1 = (const float*)d_in[9];
    const float* W2  = (const float*)d_in[10];
    const float* b2  = (const float*)d_in[11];
    const float* g2  = (const float*)d_in[12];
    const float* bt2 = (const float*)d_in[13];
    float* out = (float*)d_out;

    const int SM_PF = (64*XS_PAD + 64*WP1) * 4;
    const int SM_L1 = (64*XS_PAD + 64*WP1 + 6*64) * 4;
    const int SM_L2 = (64*XS_PAD + 64*WP2 + 2*64) * 4;
    cudaFuncSetAttribute(k_pf,     cudaFuncAttributeMaxDynamicSharedMemorySize, SM_PF);
    cudaFuncSetAttribute(k_layer1, cudaFuncAttributeMaxDynamicSharedMemorySize, SM_L1);
    cudaFuncSetAttribute(k_layer2, cudaFuncAttributeMaxDynamicSharedMemorySize, SM_L2);

    k_pf<<<NP/128, 128, SM_PF>>>(points, W0);
    k_fps<<<Bq, 512>>>(xyz, out);
    k_ball<<<NQ/QPB, BT>>>(xyz);

    k_l0stats<<<NEq/256, 256>>>(xyz, W0, b0);
    k_fin<<<64, 256>>>(g0, bt0, 0, NEq/256);
    k_layer1<<<NEq/128, 128, SM_L1>>>(xyz, W0, b0, W1, b1);
    k_fin<<<64, 256>>>(g1, bt1, 128, NEq/128);
    k_layer2<<<NEq/128, 256, SM_L2>>>(W2, b2);
    k_fin<<<128, 256>>>(g2, bt2, 256, NEq/128);
    k_maxpool<<<NQ*128/256, 256>>>(out);
}